// round 11
// baseline (speedup 1.0000x reference)
#include <cuda_runtime.h>
#include <cuda_fp16.h>
#include <cstdint>

#define NB   1024
#define TT   48
#define NPGc 32
#define FFc  5
#define HHc  512
#define EPGc 256
#define NTOT (NB*TT*NPGc)
#define ETOT (NB*TT*EPGc)
#define NGRAPH (NB*TT)
#define SEQW 160
#define TSEQ (TT*SEQW)
#define KTOT 672
#define KPAD 704                   // row stride of g_hx/g_Wc (128B aligned)
#define SLOT ((size_t)NB*KPAD)
#define NCH  8                     // h-only chunks in the serial loop
#define NGATE 2048

// dynamic smem layout for persistent lstm kernel
#define SOFF_A    1024                     // 3 stages x 16384
#define SOFF_W    (1024 + 3*16384)         // 8 chunks x 16384 = 131072
#define SOFF_PG   (SOFF_W + 8*16384)       // pregate tile 128 x 136 half = 34816
#define SMEM_SZ   (SOFF_PG + 34816)        // 216064 B

// pregate kernel smem
#define PGK_BIAS  0
#define PGK_A     1024                     // 3 x 16384
#define PGK_W     (1024 + 3*16384)         // 3 x 16384
#define PGK_SZ    (PGK_W + 3*16384)        // 99328 B

// ---------------- static device scratch --------------------------------------------
__device__ __align__(128) float  g_y  [NTOT*FFc];
__device__ __align__(128) __half g_hx [49*NB*KPAD];     // [t][B][ h(512)|seq(160)|pad(32) ]
__device__ __align__(128) __half g_Wc [4*HHc*KPAD];     // packed [Whh|Wih|0] half
__device__ __align__(128) __half g_pg [(size_t)TT*NB*NGATE]; // pregate half [t][b][R]
__device__ __align__(128) float  g_bc [4*HHc];
__device__ __align__(128) float  g_stat[NB*16];
__device__ __align__(128) unsigned g_flag[8][16];       // [mgrp][hblk] step counters
__device__ unsigned g_done = 0;

__device__ __forceinline__ float sigmf(float x){ return __fdividef(1.f, 1.f + __expf(-x)); }
__device__ __forceinline__ float tanhfast(float x){
    const float e = __expf(2.f*x);
    return 1.f - __fdividef(2.f, e + 1.f);
}

__device__ __forceinline__ void cpasync16(void* dst, const void* src){
    uint32_t d = (uint32_t)__cvta_generic_to_shared(dst);
    asm volatile("cp.async.cg.shared.global [%0], [%1], 16;\n" :: "r"(d), "l"(src));
}
__device__ __forceinline__ void cp_commit(){ asm volatile("cp.async.commit_group;\n"); }
template<int N> __device__ __forceinline__ void cp_wait(){
    asm volatile("cp.async.wait_group %0;\n" :: "n"(N));
}
__device__ __forceinline__ void ldm_x4(uint32_t* r, const void* p){
    uint32_t a = (uint32_t)__cvta_generic_to_shared(p);
    asm volatile("ldmatrix.sync.aligned.m8n8.x4.shared.b16 {%0,%1,%2,%3}, [%4];"
        : "=r"(r[0]), "=r"(r[1]), "=r"(r[2]), "=r"(r[3]) : "r"(a));
}
__device__ __forceinline__ void mma_f16(float* d, const uint32_t* a, const uint32_t* b){
    asm volatile("mma.sync.aligned.m16n8k16.row.col.f32.f16.f16.f32 "
        "{%0,%1,%2,%3}, {%4,%5,%6,%7}, {%8,%9}, {%0,%1,%2,%3};"
        : "+f"(d[0]), "+f"(d[1]), "+f"(d[2]), "+f"(d[3])
        : "r"(a[0]), "r"(a[1]), "r"(a[2]), "r"(a[3]), "r"(b[0]), "r"(b[1]));
}
__device__ __forceinline__ uint32_t swz(uint32_t off){ return off ^ ((off >> 3) & 0x70); }

// ==================== Kernel 0: pack weights (+bias) to half; zero stats =============
__global__ __launch_bounds__(256) void pack_kernel(
    const float* __restrict__ Wih, const float* __restrict__ Whh,
    const float* __restrict__ bih, const float* __restrict__ bhh)
{
    int idx = blockIdx.x*256 + threadIdx.x;
    if (idx < NB*16) g_stat[idx] = 0.f;
    const int total = 4*HHc*KPAD;
    for (; idx < total; idx += gridDim.x*256){
        const int R = idx / KPAD, k = idx - R*KPAD;
        const int hblk = R >> 7, within = R & 127;
        const int g = within >> 5, hloc = within & 31;
        const int p = g*HHc + hblk*32 + hloc;
        float v = 0.f;
        if (k < HHc)       v = Whh[(size_t)p*HHc + k];
        else if (k < KTOT) v = Wih[(size_t)p*SEQW + (k-HHc)];
        g_Wc[idx] = __float2half(v);
        if (k == 0) g_bc[R] = bih[p] + bhh[p];
    }
}

// ==================== Kernel 1: ChebConv — dense L per graph, warp per graph =========
__global__ __launch_bounds__(256) void cheb_kernel(
    const float* __restrict__ x, const float* __restrict__ ea,
    const int* __restrict__ ei, const float* __restrict__ cw,
    const float* __restrict__ cb)
{
    __shared__ float sL[8][32*33];
    __shared__ float sx[8][160], st1[8][160], sdeg[8][32];
    const int tid = threadIdx.x, lane = tid & 31, wid = tid >> 5;
    const int g  = blockIdx.x*8 + wid;
    const int nb = g * NPGc;
    const int b  = g / TT;
    float* L   = sL[wid];
    float* SX  = sx[wid];
    float* ST1 = st1[wid];
    float* SD  = sdeg[wid];

    #pragma unroll
    for (int i = 0; i < 33; ++i) L[i*32 + lane] = 0.f;
    #pragma unroll
    for (int r = 0; r < 5; ++r) SX[r*32 + lane] = x[(size_t)nb*FFc + r*32 + lane];
    SD[lane] = 0.f;
    __syncwarp();

    int es[8], ed[8];
    float ew[8];
    #pragma unroll
    for (int r = 0; r < 8; ++r){
        const int e = g*EPGc + r*32 + lane;
        es[r] = ei[e]        - nb;
        ed[r] = ei[ETOT + e] - nb;
        ew[r] = ea[e];
        atomicAdd(&SD[es[r]], ew[r]);
    }
    __syncwarp();
    {
        float dv = SD[lane];
        dv = (dv > 0.f) ? rsqrtf(dv) : 0.f;
        __syncwarp();
        SD[lane] = dv;
    }
    __syncwarp();
    #pragma unroll
    for (int r = 0; r < 8; ++r){
        const float nrm = -SD[es[r]] * ew[r] * SD[ed[r]];
        atomicAdd(&L[ed[r]*33 + es[r]], nrm);
    }
    __syncwarp();

    float t1f[5] = {0,0,0,0,0};
    #pragma unroll 4
    for (int s = 0; s < 32; ++s){
        const float l = L[lane*33 + s];
        #pragma unroll
        for (int f = 0; f < 5; ++f) t1f[f] += l * SX[s*5 + f];
    }
    #pragma unroll
    for (int f = 0; f < 5; ++f) ST1[lane*5 + f] = t1f[f];
    __syncwarp();

    float t2f[5] = {0,0,0,0,0};
    #pragma unroll 4
    for (int s = 0; s < 32; ++s){
        const float l = L[lane*33 + s];
        #pragma unroll
        for (int f = 0; f < 5; ++f) t2f[f] += l * ST1[s*5 + f];
    }
    float x0[5];
    #pragma unroll
    for (int f = 0; f < 5; ++f){
        x0[f] = SX[lane*5 + f];
        t2f[f] = 2.f*t2f[f] - x0[f];
    }

    float o[5], s2[5];
    #pragma unroll
    for (int j = 0; j < 5; ++j) o[j] = __ldg(&cb[j]);
    #pragma unroll
    for (int i = 0; i < 5; ++i){
        #pragma unroll
        for (int j = 0; j < 5; ++j)
            o[j] += x0[i]*__ldg(&cw[i*5+j]) + t1f[i]*__ldg(&cw[25+i*5+j]) + t2f[i]*__ldg(&cw[50+i*5+j]);
    }
    #pragma unroll
    for (int j = 0; j < 5; ++j){
        g_y[(size_t)nb*FFc + lane*FFc + j] = o[j];
        s2[j] = o[j]*o[j];
    }
    float s1[5];
    #pragma unroll
    for (int j = 0; j < 5; ++j) s1[j] = o[j];
    #pragma unroll
    for (int off = 16; off; off >>= 1){
        #pragma unroll
        for (int j = 0; j < 5; ++j){
            s1[j] += __shfl_xor_sync(0xffffffffu, s1[j], off);
            s2[j] += __shfl_xor_sync(0xffffffffu, s2[j], off);
        }
    }
    if (lane == 0){
        #pragma unroll
        for (int j = 0; j < 5; ++j){
            atomicAdd(&g_stat[b*16 + j],     s1[j]);
            atomicAdd(&g_stat[b*16 + 8 + j], s2[j]);
        }
    }
}

// ==================== Kernel 2: BN transform (stats precomputed) =====================
__global__ __launch_bounds__(256) void bn_kernel(
    const float* __restrict__ gamma, const float* __restrict__ beta)
{
    const int b = blockIdx.x, tid = threadIdx.x;
    __shared__ float sc[5], sh[5];
    if (tid < 5){
        const float inv = 1.f / (float)(TT*NPGc);
        const float mean = g_stat[b*16 + tid] * inv;
        const float var  = g_stat[b*16 + 8 + tid] * inv - mean*mean;
        const float scl  = gamma[tid] * rsqrtf(var + 1e-5f);
        sc[tid] = scl; sh[tid] = beta[tid] - mean*scl;
    }
    __syncthreads();
    const float* yb = g_y + (size_t)b * TSEQ;
    __half2* hz = (__half2*)(g_hx + (size_t)b*KPAD);
    for (int j = tid; j < HHc/2; j += 256) hz[j] = __half2half2(__float2half(0.f));
    for (int j = tid; j < TT*(KPAD-KTOT); j += 256){
        const int t = j / (KPAD-KTOT), c = j % (KPAD-KTOT);
        g_hx[(size_t)t*SLOT + (size_t)b*KPAD + KTOT + c] = __float2half(0.f);
    }
    for (int nidx = tid; nidx < TT*NPGc; nidx += 256){
        const int t = nidx >> 5, node = nidx & 31;
        const float* p = yb + nidx*FFc;
        __half* ob = g_hx + (size_t)t*SLOT + (size_t)b*KPAD + HHc + node*FFc;
        #pragma unroll
        for (int f = 0; f < 5; ++f) ob[f] = __float2half(sigmf(p[f]*sc[f] + sh[f]));
    }
}

// ==================== Kernel 2b: pregate = seq @ Wih^T + bias (parallel over t) ======
// grid (16 hblk, 8 mgrp, 48 t), 256 threads, tile 128x128, K = 192 (seq 160 + zero pad)
__global__ __launch_bounds__(256, 2) void pregate_kernel()
{
    extern __shared__ char smem[];
    float* sbias = (float*)(smem + PGK_BIAS);
    char*  Asm   = smem + PGK_A;
    char*  Wsm   = smem + PGK_W;

    const int tid  = threadIdx.x;
    const int lane = tid & 31, warp = tid >> 5;
    const int wm = warp >> 1, wn = warp & 1;
    const int hblk  = blockIdx.x;
    const int mbase = blockIdx.y * 128;
    const int t     = blockIdx.z;

    // W: rows hblk*128.., cols 512..704 (Wih + zero pad) — 3 chunks of 64
    for (int i = tid; i < 128*24; i += 256){
        const int r = i / 24, rem = i - r*24;
        const int ch = rem >> 3, j = rem & 7;
        cpasync16(Wsm + ch*16384 + swz((uint32_t)r*128 + j*16),
                  g_Wc + (size_t)(hblk*128 + r)*KPAD + HHc + ch*64 + j*8);
    }
    // A: rows mbase.., cols 512..704 of slot t
    const __half* Ag = g_hx + (size_t)t*SLOT + (size_t)mbase*KPAD + HHc;
    for (int i = tid; i < 128*24; i += 256){
        const int r = i / 24, rem = i - r*24;
        const int ch = rem >> 3, j = rem & 7;
        cpasync16(Asm + ch*16384 + swz((uint32_t)r*128 + j*16),
                  Ag + (size_t)r*KPAD + ch*64 + j*8);
    }
    if (tid < 128) sbias[tid] = g_bc[hblk*128 + tid];
    cp_commit();

    float acc[2][4][2][4];
    #pragma unroll
    for (int a=0;a<2;a++) for (int b=0;b<4;b++) for (int c=0;c<2;c++)
        #pragma unroll
        for (int d=0;d<4;d++) acc[a][b][c][d]=0.f;

    cp_wait<0>();
    __syncthreads();

    #pragma unroll
    for (int ch = 0; ch < 3; ++ch){
        const char* Wc = Wsm + ch*16384;
        const char* Ac = Asm + ch*16384;
        #pragma unroll
        for (int kk = 0; kk < 4; ++kk){
            uint32_t af[2][4];
            #pragma unroll
            for (int mf = 0; mf < 2; ++mf){
                const uint32_t off = (uint32_t)(wm*32 + mf*16 + (lane&15))*128
                                   + (uint32_t)(kk*16 + ((lane>>4)<<3))*2;
                ldm_x4(af[mf], Ac + swz(off));
            }
            uint32_t bf[4][4];
            #pragma unroll
            for (int g = 0; g < 4; ++g){
                const uint32_t off = (uint32_t)(g*32 + wn*16 + (lane&7) + ((lane>>4)&1)*8)*128
                                   + (uint32_t)(kk*16 + ((lane>>3)&1)*8)*2;
                ldm_x4(bf[g], Wc + swz(off));
            }
            #pragma unroll
            for (int mf = 0; mf < 2; ++mf)
                #pragma unroll
                for (int g = 0; g < 4; ++g){
                    mma_f16(acc[mf][g][0], af[mf], bf[g] + 0);
                    mma_f16(acc[mf][g][1], af[mf], bf[g] + 2);
                }
        }
    }

    // epilogue: + bias, store half to g_pg[t][row][hblk*128 + g*32 + hl]
    const int gl = lane >> 2, tl = lane & 3;
    __half* outb = g_pg + ((size_t)t*NB + mbase)*NGATE + hblk*128;
    #pragma unroll
    for (int mf = 0; mf < 2; ++mf){
        #pragma unroll
        for (int nf = 0; nf < 2; ++nf){
            const int hloc0 = wn*16 + nf*8 + tl*2;
            #pragma unroll
            for (int rr = 0; rr < 2; ++rr){
                const int rowl = wm*32 + mf*16 + gl + rr*8;
                #pragma unroll
                for (int g = 0; g < 4; ++g){
                    const float v0 = acc[mf][g][nf][rr*2+0] + sbias[g*32 + hloc0];
                    const float v1 = acc[mf][g][nf][rr*2+1] + sbias[g*32 + hloc0 + 1];
                    *(__half2*)(outb + (size_t)rowl*NGATE + g*32 + hloc0) =
                        __halves2half2(__float2half(v0), __float2half(v1));
                }
            }
        }
    }
}

// ==================== Kernel 3: persistent LSTM, 8 h-chunks + pregate ================
__global__ __launch_bounds__(256, 1) void lstm_persist_kernel()
{
    extern __shared__ char smem[];
    char* Asm = smem + SOFF_A;
    char* Wsm = smem + SOFF_W;
    char* PGs = smem + SOFF_PG;    // 128 rows x 136 half (272B row stride)

    const int tid  = threadIdx.x;
    const int lane = tid & 31, warp = tid >> 5;
    const int wm = warp >> 1, wn = warp & 1;          // 4 x 2 warp grid
    const int hblk  = blockIdx.x;                     // 16
    const int mgrp  = blockIdx.y;                     // 8
    const int mbase = mgrp * 128;
    const int hbase = hblk * 32;

    // ---- weights (128 x 512 h-part) into swizzled smem, once ----
    const __half* Bg = g_Wc + (size_t)(hblk*128)*KPAD;
    for (int i = tid; i < 128*64; i += 256){
        const int r = i >> 6, rem = i & 63;
        const int ch = rem >> 3, j = rem & 7;
        cpasync16(Wsm + ch*16384 + swz((uint32_t)r*128 + j*16),
                  Bg + (size_t)r*KPAD + ch*64 + j*8);
    }
    cp_commit();                                       // group: W

    auto fillA = [&](int chunk, int stage, const __half* Ag){
        char* dst = Asm + stage*16384;
        const __half* src = Ag + chunk*64;
        #pragma unroll
        for (int p = 0; p < 4; ++p){
            const int idx = tid + p*256;
            const int r = idx >> 3, j = idx & 7;
            cpasync16(dst + swz((uint32_t)r*128 + j*16), src + (size_t)r*KPAD + j*8);
        }
        cp_commit();
    };
    auto fillPG = [&](int t){
        const __half* src = g_pg + ((size_t)t*NB + mbase)*NGATE + hblk*128;
        #pragma unroll
        for (int k = 0; k < 8; ++k){
            const int idx = tid + k*256;
            const int r = idx >> 4, p = idx & 15;
            cpasync16(PGs + r*272 + p*16, src + (size_t)r*NGATE + p*8);
        }
        cp_commit();
    };

    // prologue for t=0 (h region of slot 0 zeroed by bn_kernel)
    {
        const __half* Ag0 = g_hx + (size_t)mbase*KPAD;
        fillPG(0);
        fillA(0, 0, Ag0);
        fillA(1, 1, Ag0);
    }

    float c_reg[2][2][4];
    #pragma unroll
    for (int a=0;a<2;a++) for (int b=0;b<2;b++) for (int e=0;e<4;e++) c_reg[a][b][e]=0.f;

    const int gl = lane >> 2, tl = lane & 3;

    for (int t = 0; t < TT; ++t){
        const __half* Ag = g_hx + (size_t)t*SLOT + (size_t)mbase*KPAD;

        float acc[2][4][2][4];
        #pragma unroll
        for (int a=0;a<2;a++) for (int b=0;b<4;b++) for (int c=0;c<2;c++)
            #pragma unroll
            for (int d=0;d<4;d++) acc[a][b][c][d]=0.f;

        for (int q = 0; q < NCH; ++q){
            if (q == NCH-1) cp_wait<0>(); else cp_wait<1>();
            __syncthreads();
            if (q + 2 < NCH) fillA(q+2, (q+2)%3, Ag);

            const char* Wc = Wsm + q*16384;
            const char* Ac = Asm + (q%3)*16384;
            #pragma unroll
            for (int kk = 0; kk < 4; ++kk){
                uint32_t af[2][4];
                #pragma unroll
                for (int mf = 0; mf < 2; ++mf){
                    const uint32_t off = (uint32_t)(wm*32 + mf*16 + (lane&15))*128
                                       + (uint32_t)(kk*16 + ((lane>>4)<<3))*2;
                    ldm_x4(af[mf], Ac + swz(off));
                }
                uint32_t bf[4][4];
                #pragma unroll
                for (int g = 0; g < 4; ++g){
                    const uint32_t off = (uint32_t)(g*32 + wn*16 + (lane&7) + ((lane>>4)&1)*8)*128
                                       + (uint32_t)(kk*16 + ((lane>>3)&1)*8)*2;
                    ldm_x4(bf[g], Wc + swz(off));
                }
                #pragma unroll
                for (int mf = 0; mf < 2; ++mf)
                    #pragma unroll
                    for (int g = 0; g < 4; ++g){
                        mma_f16(acc[mf][g][0], af[mf], bf[g] + 0);
                        mma_f16(acc[mf][g][1], af[mf], bf[g] + 2);
                    }
            }
        }

        // epilogue: gates = acc + pregate(smem); c in regs; h (half) into slot t+1
        __half* h_out = g_hx + (size_t)(t+1)*SLOT;
        #pragma unroll
        for (int mf = 0; mf < 2; ++mf){
            #pragma unroll
            for (int nf = 0; nf < 2; ++nf){
                const int hloc0 = wn*16 + nf*8 + tl*2;
                #pragma unroll
                for (int rr = 0; rr < 2; ++rr){
                    const int rowl = wm*32 + mf*16 + gl + rr*8;
                    const int row  = mbase + rowl;
                    const char* pgrow = PGs + rowl*272;
                    float2 pg[4];
                    #pragma unroll
                    for (int g = 0; g < 4; ++g)
                        pg[g] = __half22float2(*(const __half2*)(pgrow + (g*32 + hloc0)*2));
                    float hv[2];
                    #pragma unroll
                    for (int j = 0; j < 2; ++j){
                        const int e = rr*2 + j;
                        const float iv = acc[mf][0][nf][e] + (j ? pg[0].y : pg[0].x);
                        const float fv = acc[mf][1][nf][e] + (j ? pg[1].y : pg[1].x);
                        const float gv = acc[mf][2][nf][e] + (j ? pg[2].y : pg[2].x);
                        const float ov = acc[mf][3][nf][e] + (j ? pg[3].y : pg[3].x);
                        const float cn = sigmf(fv)*c_reg[mf][nf][e] + sigmf(iv)*tanhfast(gv);
                        c_reg[mf][nf][e] = cn;
                        hv[j] = sigmf(ov)*tanhfast(cn);
                    }
                    *(__half2*)(h_out + (size_t)row*KPAD + hbase + hloc0) =
                        __halves2half2(__float2half(hv[0]), __float2half(hv[1]));
                }
            }
        }

        __syncthreads();   // epilogue PG reads done; h stores issued

        if (t + 1 < TT){
            if (tid == 0){
                __threadfence();
                asm volatile("st.relaxed.gpu.u32 [%0], %1;"
                    :: "l"(&g_flag[mgrp][hblk]), "r"((unsigned)(t+1)) : "memory");
            }
            // pregate fill for t+1 is independent of h — overlaps the flag wait
            fillPG(t+1);
            // wait for all 16 producers of this m-group to publish step t+1 h
            {
                const unsigned* fp = &g_flag[mgrp][0];
                unsigned ok;
                do {
                    unsigned f0,f1,f2,f3,f4,f5,f6,f7;
                    asm volatile("ld.relaxed.gpu.v4.u32 {%0,%1,%2,%3}, [%4];"
                        : "=r"(f0),"=r"(f1),"=r"(f2),"=r"(f3) : "l"(fp));
                    asm volatile("ld.relaxed.gpu.v4.u32 {%0,%1,%2,%3}, [%4];"
                        : "=r"(f4),"=r"(f5),"=r"(f6),"=r"(f7) : "l"(fp+4));
                    unsigned g0,g1,g2,g3,g4,g5,g6,g7;
                    asm volatile("ld.relaxed.gpu.v4.u32 {%0,%1,%2,%3}, [%4];"
                        : "=r"(g0),"=r"(g1),"=r"(g2),"=r"(g3) : "l"(fp+8));
                    asm volatile("ld.relaxed.gpu.v4.u32 {%0,%1,%2,%3}, [%4];"
                        : "=r"(g4),"=r"(g5),"=r"(g6),"=r"(g7) : "l"(fp+12));
                    unsigned mn = min(min(min(f0,f1),min(f2,f3)), min(min(f4,f5),min(f6,f7)));
                    mn = min(mn, min(min(min(g0,g1),min(g2,g3)), min(min(g4,g5),min(g6,g7))));
                    ok = (mn >= (unsigned)(t+1));
                } while (!ok);
                __threadfence();
            }
            const __half* Agn = g_hx + (size_t)(t+1)*SLOT + (size_t)mbase*KPAD;
            fillA(0, 0, Agn);
            fillA(1, 1, Agn);
        }
    }

    // reset flags for the next replay (last block to finish)
    __syncthreads();
    if (tid == 0){
        const unsigned d = atomicAdd(&g_done, 1u);
        if (d == 127u){
            for (int i = 0; i < 8; ++i)
                for (int j = 0; j < 16; ++j) g_flag[i][j] = 0u;
            g_done = 0u;
            __threadfence();
        }
    }
}

// ==================== Kernel 4: final linear, 4 samples per block (R6 version) =======
__global__ __launch_bounds__(256) void final_kernel(
    const float* __restrict__ linW, const float* __restrict__ linb,
    float* __restrict__ outp)
{
    const int tid = threadIdx.x, lane = tid & 31, warp = tid >> 5;
    const int b0 = blockIdx.x * 4;
    float acc[4][4];
    #pragma unroll
    for (int s = 0; s < 4; ++s)
        #pragma unroll
        for (int o = 0; o < 4; ++o) acc[s][o] = 0.f;

    for (int idx = tid; idx < TT*HHc; idx += 256){
        const int tq = idx >> 9, h = idx & 511;
        const float w0 = __ldg(&linW[idx]);
        const float w1 = __ldg(&linW[TT*HHc + idx]);
        const float w2 = __ldg(&linW[2*TT*HHc + idx]);
        const float w3 = __ldg(&linW[3*TT*HHc + idx]);
        const __half* hp = g_hx + (size_t)(tq+1)*SLOT + h;
        #pragma unroll
        for (int s = 0; s < 4; ++s){
            const float v = sigmf(__half2float(hp[(size_t)(b0+s)*KPAD]));
            acc[s][0] += v*w0; acc[s][1] += v*w1;
            acc[s][2] += v*w2; acc[s][3] += v*w3;
        }
    }
    #pragma unroll
    for (int off = 16; off; off >>= 1)
        #pragma unroll
        for (int s = 0; s < 4; ++s)
            #pragma unroll
            for (int o = 0; o < 4; ++o)
                acc[s][o] += __shfl_xor_sync(0xffffffffu, acc[s][o], off);

    __shared__ float red[8][16];
    if (lane == 0){
        #pragma unroll
        for (int s = 0; s < 4; ++s)
            #pragma unroll
            for (int o = 0; o < 4; ++o) red[warp][s*4+o] = acc[s][o];
    }
    __syncthreads();
    if (tid < 16){
        float sum = 0.f;
        #pragma unroll
        for (int w = 0; w < 8; ++w) sum += red[w][tid];
        const int s = tid >> 2, o = tid & 3;
        outp[(b0 + s)*4 + o] = sigmf(sum + __ldg(&linb[o]));
    }
}

// =====================================================================================
extern "C" void kernel_launch(void* const* d_in, const int* in_sizes, int n_in,
                              void* d_out, int out_size)
{
    const float* x     = (const float*)d_in[0];
    const float* ea    = (const float*)d_in[1];
    const float* cw    = (const float*)d_in[2];
    const float* cb    = (const float*)d_in[3];
    const float* gamma = (const float*)d_in[4];
    const float* beta  = (const float*)d_in[5];
    const float* Wih   = (const float*)d_in[6];
    const float* Whh   = (const float*)d_in[7];
    const float* bih   = (const float*)d_in[8];
    const float* bhh   = (const float*)d_in[9];
    const float* linW  = (const float*)d_in[10];
    const float* linb  = (const float*)d_in[11];
    const int*   ei    = (const int*)  d_in[12];
    float* outp = (float*)d_out;

    cudaFuncSetAttribute(lstm_persist_kernel,
        cudaFuncAttributeMaxDynamicSharedMemorySize, SMEM_SZ);
    cudaFuncSetAttribute(pregate_kernel,
        cudaFuncAttributeMaxDynamicSharedMemorySize, PGK_SZ);

    pack_kernel<<<1024, 256>>>(Wih, Whh, bih, bhh);
    cheb_kernel<<<NGRAPH/8, 256>>>(x, ea, ei, cw, cb);
    bn_kernel<<<NB, 256>>>(gamma, beta);
    pregate_kernel<<<dim3(16, 8, TT), 256, PGK_SZ>>>();
    lstm_persist_kernel<<<dim3(16, 8), 256, SMEM_SZ>>>();
    final_kernel<<<NB/4, 256>>>(linW, linb, outp);
}

// round 12
// speedup vs baseline: 1.6327x; 1.6327x over previous
#include <cuda_runtime.h>
#include <cuda_fp16.h>
#include <cstdint>

#define NB   1024
#define TT   48
#define NPGc 32
#define FFc  5
#define HHc  512
#define EPGc 256
#define NTOT (NB*TT*NPGc)
#define ETOT (NB*TT*EPGc)
#define NGRAPH (NB*TT)
#define SEQW 160
#define TSEQ (TT*SEQW)
#define KTOT 672
#define KPAD 704                   // 11 full chunks of 64, 128B-aligned rows
#define SLOT ((size_t)NB*KPAD)
#define NCHUNK 11

// dynamic smem layout for lstm kernel
#define SOFF_BIAS 0                // 512 B
#define SOFF_A    1024             // 3 stages x 16384
#define SOFF_W    (1024 + 3*16384) // 11 chunks x 16384
#define SMEM_SZ   (SOFF_W + NCHUNK*16384)   // 230400 B

// ---------------- static device scratch --------------------------------------------
__device__ __align__(128) float  g_y  [NTOT*FFc];
__device__ __align__(128) __half g_hx [49*NB*KPAD];   // [t][B][ h(512) | seq(160) | pad ]
__device__ __align__(128) __half g_Wc [4*HHc*KPAD];   // packed [Whh|Wih|0] half
__device__ __align__(128) float  g_bc [4*HHc];
__device__ __align__(128) float  g_stat[NB*16];
__device__ __align__(128) float  g_part[TT*NB*4];     // [t][b][4] final partials
__device__ __align__(128) unsigned g_flag[8][16];     // [mgrp][hblk] step counters
__device__ unsigned g_done = 0;

__device__ __forceinline__ float sigmf(float x){ return __fdividef(1.f, 1.f + __expf(-x)); }
__device__ __forceinline__ float tanhfast(float x){
    const float e = __expf(2.f*x);
    return 1.f - __fdividef(2.f, e + 1.f);
}

__device__ __forceinline__ void cpasync16(void* dst, const void* src){
    uint32_t d = (uint32_t)__cvta_generic_to_shared(dst);
    asm volatile("cp.async.cg.shared.global [%0], [%1], 16;\n" :: "r"(d), "l"(src));
}
__device__ __forceinline__ void cp_commit(){ asm volatile("cp.async.commit_group;\n"); }
template<int N> __device__ __forceinline__ void cp_wait(){
    asm volatile("cp.async.wait_group %0;\n" :: "n"(N));
}
__device__ __forceinline__ void ldm_x4(uint32_t* r, const void* p){
    uint32_t a = (uint32_t)__cvta_generic_to_shared(p);
    asm volatile("ldmatrix.sync.aligned.m8n8.x4.shared.b16 {%0,%1,%2,%3}, [%4];"
        : "=r"(r[0]), "=r"(r[1]), "=r"(r[2]), "=r"(r[3]) : "r"(a));
}
__device__ __forceinline__ void mma_f16(float* d, const uint32_t* a, const uint32_t* b){
    asm volatile("mma.sync.aligned.m16n8k16.row.col.f32.f16.f16.f32 "
        "{%0,%1,%2,%3}, {%4,%5,%6,%7}, {%8,%9}, {%0,%1,%2,%3};"
        : "+f"(d[0]), "+f"(d[1]), "+f"(d[2]), "+f"(d[3])
        : "r"(a[0]), "r"(a[1]), "r"(a[2]), "r"(a[3]), "r"(b[0]), "r"(b[1]));
}
__device__ __forceinline__ uint32_t swz(uint32_t off){ return off ^ ((off >> 3) & 0x70); }

// ==================== Kernel 0: pack weights (+bias) to half; zero stats =============
__global__ __launch_bounds__(256) void pack_kernel(
    const float* __restrict__ Wih, const float* __restrict__ Whh,
    const float* __restrict__ bih, const float* __restrict__ bhh)
{
    int idx = blockIdx.x*256 + threadIdx.x;
    if (idx < NB*16) g_stat[idx] = 0.f;
    const int total = 4*HHc*KPAD;
    for (; idx < total; idx += gridDim.x*256){
        const int R = idx / KPAD, k = idx - R*KPAD;
        const int hblk = R >> 7, within = R & 127;
        const int g = within >> 5, hloc = within & 31;
        const int p = g*HHc + hblk*32 + hloc;
        float v = 0.f;
        if (k < HHc)       v = Whh[(size_t)p*HHc + k];
        else if (k < KTOT) v = Wih[(size_t)p*SEQW + (k-HHc)];
        g_Wc[idx] = __float2half(v);
        if (k == 0) g_bc[R] = bih[p] + bhh[p];
    }
}

// ==================== Kernel 1: ChebConv — dense L per graph, warp per graph =========
__global__ __launch_bounds__(256) void cheb_kernel(
    const float* __restrict__ x, const float* __restrict__ ea,
    const int* __restrict__ ei, const float* __restrict__ cw,
    const float* __restrict__ cb)
{
    __shared__ float sL[8][32*33];
    __shared__ float sx[8][160], st1[8][160], sdeg[8][32];
    const int tid = threadIdx.x, lane = tid & 31, wid = tid >> 5;
    const int g  = blockIdx.x*8 + wid;
    const int nb = g * NPGc;
    const int b  = g / TT;
    float* L   = sL[wid];
    float* SX  = sx[wid];
    float* ST1 = st1[wid];
    float* SD  = sdeg[wid];

    #pragma unroll
    for (int i = 0; i < 33; ++i) L[i*32 + lane] = 0.f;
    #pragma unroll
    for (int r = 0; r < 5; ++r) SX[r*32 + lane] = x[(size_t)nb*FFc + r*32 + lane];
    SD[lane] = 0.f;
    __syncwarp();

    int es[8], ed[8];
    float ew[8];
    #pragma unroll
    for (int r = 0; r < 8; ++r){
        const int e = g*EPGc + r*32 + lane;
        es[r] = ei[e]        - nb;
        ed[r] = ei[ETOT + e] - nb;
        ew[r] = ea[e];
        atomicAdd(&SD[es[r]], ew[r]);
    }
    __syncwarp();
    {
        float dv = SD[lane];
        dv = (dv > 0.f) ? rsqrtf(dv) : 0.f;
        __syncwarp();
        SD[lane] = dv;
    }
    __syncwarp();
    #pragma unroll
    for (int r = 0; r < 8; ++r){
        const float nrm = -SD[es[r]] * ew[r] * SD[ed[r]];
        atomicAdd(&L[ed[r]*33 + es[r]], nrm);
    }
    __syncwarp();

    float t1f[5] = {0,0,0,0,0};
    #pragma unroll 4
    for (int s = 0; s < 32; ++s){
        const float l = L[lane*33 + s];
        #pragma unroll
        for (int f = 0; f < 5; ++f) t1f[f] += l * SX[s*5 + f];
    }
    #pragma unroll
    for (int f = 0; f < 5; ++f) ST1[lane*5 + f] = t1f[f];
    __syncwarp();

    float t2f[5] = {0,0,0,0,0};
    #pragma unroll 4
    for (int s = 0; s < 32; ++s){
        const float l = L[lane*33 + s];
        #pragma unroll
        for (int f = 0; f < 5; ++f) t2f[f] += l * ST1[s*5 + f];
    }
    float x0[5];
    #pragma unroll
    for (int f = 0; f < 5; ++f){
        x0[f] = SX[lane*5 + f];
        t2f[f] = 2.f*t2f[f] - x0[f];
    }

    float o[5], s2[5];
    #pragma unroll
    for (int j = 0; j < 5; ++j) o[j] = __ldg(&cb[j]);
    #pragma unroll
    for (int i = 0; i < 5; ++i){
        #pragma unroll
        for (int j = 0; j < 5; ++j)
            o[j] += x0[i]*__ldg(&cw[i*5+j]) + t1f[i]*__ldg(&cw[25+i*5+j]) + t2f[i]*__ldg(&cw[50+i*5+j]);
    }
    #pragma unroll
    for (int j = 0; j < 5; ++j){
        g_y[(size_t)nb*FFc + lane*FFc + j] = o[j];
        s2[j] = o[j]*o[j];
    }
    float s1[5];
    #pragma unroll
    for (int j = 0; j < 5; ++j) s1[j] = o[j];
    #pragma unroll
    for (int off = 16; off; off >>= 1){
        #pragma unroll
        for (int j = 0; j < 5; ++j){
            s1[j] += __shfl_xor_sync(0xffffffffu, s1[j], off);
            s2[j] += __shfl_xor_sync(0xffffffffu, s2[j], off);
        }
    }
    if (lane == 0){
        #pragma unroll
        for (int j = 0; j < 5; ++j){
            atomicAdd(&g_stat[b*16 + j],     s1[j]);
            atomicAdd(&g_stat[b*16 + 8 + j], s2[j]);
        }
    }
}

// ==================== Kernel 2: BN transform (stats precomputed) =====================
__global__ __launch_bounds__(256) void bn_kernel(
    const float* __restrict__ gamma, const float* __restrict__ beta)
{
    const int b = blockIdx.x, tid = threadIdx.x;
    __shared__ float sc[5], sh[5];
    if (tid < 5){
        const float inv = 1.f / (float)(TT*NPGc);
        const float mean = g_stat[b*16 + tid] * inv;
        const float var  = g_stat[b*16 + 8 + tid] * inv - mean*mean;
        const float scl  = gamma[tid] * rsqrtf(var + 1e-5f);
        sc[tid] = scl; sh[tid] = beta[tid] - mean*scl;
    }
    __syncthreads();
    const float* yb = g_y + (size_t)b * TSEQ;
    __half2* hz = (__half2*)(g_hx + (size_t)b*KPAD);
    for (int j = tid; j < HHc/2; j += 256) hz[j] = __half2half2(__float2half(0.f));
    for (int j = tid; j < TT*(KPAD-KTOT); j += 256){
        const int t = j / (KPAD-KTOT), c = j % (KPAD-KTOT);
        g_hx[(size_t)t*SLOT + (size_t)b*KPAD + KTOT + c] = __float2half(0.f);
    }
    for (int nidx = tid; nidx < TT*NPGc; nidx += 256){
        const int t = nidx >> 5, node = nidx & 31;
        const float* p = yb + nidx*FFc;
        __half* ob = g_hx + (size_t)t*SLOT + (size_t)b*KPAD + HHc + node*FFc;
        #pragma unroll
        for (int f = 0; f < 5; ++f) ob[f] = __float2half(sigmf(p[f]*sc[f] + sh[f]));
    }
}

// ==================== Kernel 3: persistent LSTM (exact round-10 core) ================
__global__ __launch_bounds__(256, 1) void lstm_persist_kernel()
{
    extern __shared__ char smem[];
    float* sbias = (float*)(smem + SOFF_BIAS);
    char*  Asm   = smem + SOFF_A;
    char*  Wsm   = smem + SOFF_W;

    const int tid  = threadIdx.x;
    const int lane = tid & 31, warp = tid >> 5;
    const int wm = warp >> 1, wn = warp & 1;          // 4 x 2 warp grid
    const int hblk  = blockIdx.x;                     // 16
    const int mgrp  = blockIdx.y;                     // 8
    const int mbase = mgrp * 128;
    const int hbase = hblk * 32;

    // ---- weights (128 x 704 half) into swizzled smem, once ----
    const __half* Bg = g_Wc + (size_t)(hblk*128)*KPAD;
    for (int i = tid; i < 128*NCHUNK*8; i += 256){
        const int r = i / (NCHUNK*8);
        const int rem = i - r*(NCHUNK*8);
        const int c = rem >> 3, j = rem & 7;
        cpasync16(Wsm + c*16384 + swz((uint32_t)r*128 + j*16),
                  Bg + (size_t)r*KPAD + c*64 + j*8);
    }
    if (tid < 128) sbias[tid] = g_bc[hblk*128 + tid];
    cp_commit();                                       // group: W

    auto fillA = [&](int chunk, int stage, const __half* Ag){
        char* dst = Asm + stage*16384;
        const __half* src = Ag + chunk*64;
        #pragma unroll
        for (int p = 0; p < 4; ++p){
            const int idx = tid + p*256;
            const int r = idx >> 3, j = idx & 7;
            cpasync16(dst + swz((uint32_t)r*128 + j*16), src + (size_t)r*KPAD + j*8);
        }
        cp_commit();
    };

    // prologue: step 0 chunks 8,9 -> stages 0,1
    {
        const __half* Ag0 = g_hx + (size_t)mbase*KPAD;
        fillA(8, 0, Ag0);
        fillA(9, 1, Ag0);
    }

    float c_reg[2][2][4];
    #pragma unroll
    for (int a=0;a<2;a++) for (int b=0;b<2;b++) for (int e=0;e<4;e++) c_reg[a][b][e]=0.f;

    const int gl = lane >> 2, tl = lane & 3;
    int stg = 0;   // stage of chunk being computed this iteration

    for (int t = 0; t < TT; ++t){
        const __half* Ag  = g_hx + (size_t)t*SLOT + (size_t)mbase*KPAD;
        const __half* Agn = g_hx + (size_t)(t+1)*SLOT + (size_t)mbase*KPAD;

        float acc[2][4][2][4];
        #pragma unroll
        for (int a=0;a<2;a++) for (int b=0;b<4;b++) for (int c=0;c<2;c++)
            #pragma unroll
            for (int d=0;d<4;d++) acc[a][b][c][d]=0.f;

        for (int q = 0; q < NCHUNK; ++q){
            if (t == TT-1 && q == NCHUNK-1) cp_wait<0>(); else cp_wait<1>();
            __syncthreads();

            // issue fill for iteration q+2 (stage (stg+2)%3)
            if (!(t == TT-1 && q >= 9)){
                const int fstage = (stg + 2 >= 3) ? stg - 1 : stg + 2;
                if (q == 0){
                    fillA(10, fstage, Ag);
                } else if (q <= 8){
                    if (q == 1 && t > 0){
                        // wait for all 16 producers of this m-group to publish step t h
                        const unsigned* fp = &g_flag[mgrp][0];
                        unsigned ok;
                        do {
                            unsigned f0,f1,f2,f3,f4,f5,f6,f7;
                            asm volatile("ld.relaxed.gpu.v4.u32 {%0,%1,%2,%3}, [%4];"
                                : "=r"(f0),"=r"(f1),"=r"(f2),"=r"(f3) : "l"(fp));
                            asm volatile("ld.relaxed.gpu.v4.u32 {%0,%1,%2,%3}, [%4];"
                                : "=r"(f4),"=r"(f5),"=r"(f6),"=r"(f7) : "l"(fp+4));
                            unsigned g0,g1,g2,g3,g4,g5,g6,g7;
                            asm volatile("ld.relaxed.gpu.v4.u32 {%0,%1,%2,%3}, [%4];"
                                : "=r"(g0),"=r"(g1),"=r"(g2),"=r"(g3) : "l"(fp+8));
                            asm volatile("ld.relaxed.gpu.v4.u32 {%0,%1,%2,%3}, [%4];"
                                : "=r"(g4),"=r"(g5),"=r"(g6),"=r"(g7) : "l"(fp+12));
                            unsigned mn = min(min(min(f0,f1),min(f2,f3)), min(min(f4,f5),min(f6,f7)));
                            mn = min(mn, min(min(min(g0,g1),min(g2,g3)), min(min(g4,g5),min(g6,g7))));
                            ok = (mn >= (unsigned)t);
                        } while (!ok);
                        __threadfence();
                    }
                    fillA(q-1, fstage, Ag);            // h chunks 0..7 of step t
                } else {
                    fillA(q-1, fstage, Agn);           // chunks 8,9 of step t+1 (seq only)
                }
            }

            // compute chunk order[q] from stage stg
            const int c = (q < 3) ? q + 8 : q - 3;
            const char* Wc = Wsm + c*16384;
            const char* Ac = Asm + stg*16384;
            #pragma unroll
            for (int kk = 0; kk < 4; ++kk){
                uint32_t af[2][4];
                #pragma unroll
                for (int mf = 0; mf < 2; ++mf){
                    const uint32_t off = (uint32_t)(wm*32 + mf*16 + (lane&15))*128
                                       + (uint32_t)(kk*16 + ((lane>>4)<<3))*2;
                    ldm_x4(af[mf], Ac + swz(off));
                }
                uint32_t bf[4][4];
                #pragma unroll
                for (int g = 0; g < 4; ++g){
                    const uint32_t off = (uint32_t)(g*32 + wn*16 + (lane&7) + ((lane>>4)&1)*8)*128
                                       + (uint32_t)(kk*16 + ((lane>>3)&1)*8)*2;
                    ldm_x4(bf[g], Wc + swz(off));
                }
                #pragma unroll
                for (int mf = 0; mf < 2; ++mf)
                    #pragma unroll
                    for (int g = 0; g < 4; ++g){
                        mma_f16(acc[mf][g][0], af[mf], bf[g] + 0);
                        mma_f16(acc[mf][g][1], af[mf], bf[g] + 2);
                    }
            }
            stg = (stg + 1 >= 3) ? 0 : stg + 1;
        }

        // epilogue: gates -> c (regs) -> h (half) into slot t+1
        __half* h_out = g_hx + (size_t)(t+1)*SLOT;
        #pragma unroll
        for (int mf = 0; mf < 2; ++mf){
            #pragma unroll
            for (int nf = 0; nf < 2; ++nf){
                const int hloc0 = wn*16 + nf*8 + tl*2;
                #pragma unroll
                for (int rr = 0; rr < 2; ++rr){
                    const int row = mbase + wm*32 + mf*16 + gl + rr*8;
                    float hv[2];
                    #pragma unroll
                    for (int j = 0; j < 2; ++j){
                        const int e = rr*2 + j;
                        const int hl = hloc0 + j;
                        const float iv = acc[mf][0][nf][e] + sbias[hl];
                        const float fv = acc[mf][1][nf][e] + sbias[32 + hl];
                        const float gv = acc[mf][2][nf][e] + sbias[64 + hl];
                        const float ov = acc[mf][3][nf][e] + sbias[96 + hl];
                        const float cn = sigmf(fv)*c_reg[mf][nf][e] + sigmf(iv)*tanhfast(gv);
                        c_reg[mf][nf][e] = cn;
                        hv[j] = sigmf(ov)*tanhfast(cn);
                    }
                    *(__half2*)(h_out + (size_t)row*KPAD + hbase + hloc0) =
                        __halves2half2(__float2half(hv[0]), __float2half(hv[1]));
                }
            }
        }

        // publish h for step t+1 consumers
        __syncthreads();
        if (tid == 0){
            __threadfence();
            asm volatile("st.relaxed.gpu.u32 [%0], %1;"
                :: "l"(&g_flag[mgrp][hblk]), "r"((unsigned)(t+1)) : "memory");
        }
    }

    // reset flags for the next replay (last block to finish)
    __syncthreads();
    if (tid == 0){
        const unsigned d = atomicAdd(&g_done, 1u);
        if (d == 127u){
            for (int i = 0; i < 8; ++i)
                for (int j = 0; j < 16; ++j) g_flag[i][j] = 0u;
            g_done = 0u;
            __threadfence();
        }
    }
}

// ==================== Kernel 4a: final linear partials, split over t =================
// grid (TT, 8): block (t, mgrp) computes partial[t][row][o] for 128 rows.
__global__ __launch_bounds__(256) void final_part_kernel(const float* __restrict__ linW)
{
    __shared__ float slw[4*HHc];       // linW slice for this t: [o][512]
    const int tid = threadIdx.x;
    const int t = blockIdx.x, mbase = blockIdx.y * 128;

    #pragma unroll
    for (int i = 0; i < 8; ++i){
        const int idx = tid + i*256;            // 2048 floats
        const int o = idx >> 9, h = idx & 511;
        slw[idx] = __ldg(&linW[(size_t)o*(TT*HHc) + t*HHc + h]);
    }
    __syncthreads();

    const int rowl = tid >> 1, half = tid & 1;
    const int h0 = half * 256;
    const __half* hp = g_hx + (size_t)(t+1)*SLOT + (size_t)(mbase + rowl)*KPAD + h0;

    float acc[4] = {0.f, 0.f, 0.f, 0.f};
    #pragma unroll 4
    for (int it = 0; it < 32; ++it){
        const uint4 pk = *(const uint4*)(hp + it*8);
        const __half2* h2 = (const __half2*)&pk;
        #pragma unroll
        for (int p = 0; p < 4; ++p){
            const float2 vv = __half22float2(h2[p]);
            const int h = h0 + it*8 + p*2;
            const float v0 = sigmf(vv.x), v1 = sigmf(vv.y);
            #pragma unroll
            for (int o = 0; o < 4; ++o)
                acc[o] += v0*slw[o*HHc + h] + v1*slw[o*HHc + h + 1];
        }
    }
    // combine the two h-halves of the row (lanes tid, tid^1)
    #pragma unroll
    for (int o = 0; o < 4; ++o)
        acc[o] += __shfl_xor_sync(0xffffffffu, acc[o], 1);

    if (half == 0){
        float4 w = make_float4(acc[0], acc[1], acc[2], acc[3]);
        *(float4*)(g_part + ((size_t)t*NB + mbase + rowl)*4) = w;
    }
}

// ==================== Kernel 4b: finish — sum partials over t, sigmoid ===============
__global__ __launch_bounds__(256) void final_finish_kernel(
    const float* __restrict__ linb, float* __restrict__ outp)
{
    const int gid = blockIdx.x*256 + threadIdx.x;   // 0..4095
    if (gid >= NB*4) return;
    const int o = gid & 3;
    float sum = 0.f;
    #pragma unroll
    for (int t = 0; t < TT; ++t) sum += g_part[(size_t)t*NB*4 + gid];
    outp[gid] = sigmf(sum + __ldg(&linb[o]));
}

// =====================================================================================
extern "C" void kernel_launch(void* const* d_in, const int* in_sizes, int n_in,
                              void* d_out, int out_size)
{
    const float* x     = (const float*)d_in[0];
    const float* ea    = (const float*)d_in[1];
    const float* cw    = (const float*)d_in[2];
    const float* cb    = (const float*)d_in[3];
    const float* gamma = (const float*)d_in[4];
    const float* beta  = (const float*)d_in[5];
    const float* Wih   = (const float*)d_in[6];
    const float* Whh   = (const float*)d_in[7];
    const float* bih   = (const float*)d_in[8];
    const float* bhh   = (const float*)d_in[9];
    const float* linW  = (const float*)d_in[10];
    const float* linb  = (const float*)d_in[11];
    const int*   ei    = (const int*)  d_in[12];
    float* outp = (float*)d_out;

    cudaFuncSetAttribute(lstm_persist_kernel,
        cudaFuncAttributeMaxDynamicSharedMemorySize, SMEM_SZ);

    pack_kernel<<<1024, 256>>>(Wih, Whh, bih, bhh);
    cheb_kernel<<<NGRAPH/8, 256>>>(x, ea, ei, cw, cb);
    bn_kernel<<<NB, 256>>>(gamma, beta);
    lstm_persist_kernel<<<dim3(16, 8), 256, SMEM_SZ>>>();
    final_part_kernel<<<dim3(TT, 8), 256>>>(linW);
    final_finish_kernel<<<16, 256>>>(linb, outp);
}

// round 13
// speedup vs baseline: 1.7770x; 1.0884x over previous
#include <cuda_runtime.h>
#include <cuda_fp16.h>
#include <cstdint>

#define NB   1024
#define TT   48
#define NPGc 32
#define FFc  5
#define HHc  512
#define EPGc 256
#define NTOT (NB*TT*NPGc)
#define ETOT (NB*TT*EPGc)
#define NGRAPH (NB*TT)
#define SEQW 160
#define TSEQ (TT*SEQW)
#define KTOT 672
#define KPAD 704                   // 11 full chunks of 64, 128B-aligned rows
#define SLOT ((size_t)NB*KPAD)
#define NCHUNK 11

// dynamic smem layout for lstm kernel
#define SOFF_BIAS 0                // 512 B
#define SOFF_A    1024             // 3 stages x 16384
#define SOFF_W    (1024 + 3*16384) // 11 chunks x 16384
#define SMEM_SZ   (SOFF_W + NCHUNK*16384)   // 230400 B

// ---------------- static device scratch --------------------------------------------
__device__ __align__(128) float  g_y  [NTOT*FFc];
__device__ __align__(128) __half g_hx [49*NB*KPAD];   // [t][B][ h(512) | seq(160) | pad ]
__device__ __align__(128) __half g_Wc [4*HHc*KPAD];   // packed [Whh|Wih|0] half
__device__ __align__(128) float  g_bc [4*HHc];
__device__ __align__(128) float  g_stat[NB*16];
__device__ __align__(128) float  g_part[TT*NB*4];     // [t][b][4] final partials
__device__ __align__(128) unsigned g_flag[8][16];     // [mgrp][hblk] step counters
__device__ unsigned g_done = 0;

// HW tanh (sm_75+): 1 MUFU op; sigmoid via tanh identity (1 MUFU + FMA)
__device__ __forceinline__ float tanha(float x){
    float r; asm("tanh.approx.f32 %0, %1;" : "=f"(r) : "f"(x)); return r;
}
__device__ __forceinline__ float sigmf(float x){ return fmaf(0.5f, tanha(0.5f*x), 0.5f); }
__device__ __forceinline__ float tanhfast(float x){ return tanha(x); }

__device__ __forceinline__ void cpasync16(void* dst, const void* src){
    uint32_t d = (uint32_t)__cvta_generic_to_shared(dst);
    asm volatile("cp.async.cg.shared.global [%0], [%1], 16;\n" :: "r"(d), "l"(src));
}
__device__ __forceinline__ void cp_commit(){ asm volatile("cp.async.commit_group;\n"); }
template<int N> __device__ __forceinline__ void cp_wait(){
    asm volatile("cp.async.wait_group %0;\n" :: "n"(N));
}
__device__ __forceinline__ void ldm_x4(uint32_t* r, const void* p){
    uint32_t a = (uint32_t)__cvta_generic_to_shared(p);
    asm volatile("ldmatrix.sync.aligned.m8n8.x4.shared.b16 {%0,%1,%2,%3}, [%4];"
        : "=r"(r[0]), "=r"(r[1]), "=r"(r[2]), "=r"(r[3]) : "r"(a));
}
__device__ __forceinline__ void mma_f16(float* d, const uint32_t* a, const uint32_t* b){
    asm volatile("mma.sync.aligned.m16n8k16.row.col.f32.f16.f16.f32 "
        "{%0,%1,%2,%3}, {%4,%5,%6,%7}, {%8,%9}, {%0,%1,%2,%3};"
        : "+f"(d[0]), "+f"(d[1]), "+f"(d[2]), "+f"(d[3])
        : "r"(a[0]), "r"(a[1]), "r"(a[2]), "r"(a[3]), "r"(b[0]), "r"(b[1]));
}
__device__ __forceinline__ uint32_t swz(uint32_t off){ return off ^ ((off >> 3) & 0x70); }

// ==================== Kernel 0: pack weights (+bias) to half; zero stats =============
__global__ __launch_bounds__(256) void pack_kernel(
    const float* __restrict__ Wih, const float* __restrict__ Whh,
    const float* __restrict__ bih, const float* __restrict__ bhh)
{
    int idx = blockIdx.x*256 + threadIdx.x;
    if (idx < NB*16) g_stat[idx] = 0.f;
    const int total = 4*HHc*KPAD;
    for (; idx < total; idx += gridDim.x*256){
        const int R = idx / KPAD, k = idx - R*KPAD;
        const int hblk = R >> 7, within = R & 127;
        const int g = within >> 5, hloc = within & 31;
        const int p = g*HHc + hblk*32 + hloc;
        float v = 0.f;
        if (k < HHc)       v = Whh[(size_t)p*HHc + k];
        else if (k < KTOT) v = Wih[(size_t)p*SEQW + (k-HHc)];
        g_Wc[idx] = __float2half(v);
        if (k == 0) g_bc[R] = bih[p] + bhh[p];
    }
}

// ==================== Kernel 1: ChebConv — dense L per graph, warp per graph =========
__global__ __launch_bounds__(256) void cheb_kernel(
    const float* __restrict__ x, const float* __restrict__ ea,
    const int* __restrict__ ei, const float* __restrict__ cw,
    const float* __restrict__ cb)
{
    __shared__ float sL[8][32*33];
    __shared__ float sx[8][160], st1[8][160], sdeg[8][32];
    const int tid = threadIdx.x, lane = tid & 31, wid = tid >> 5;
    const int g  = blockIdx.x*8 + wid;
    const int nb = g * NPGc;
    const int b  = g / TT;
    float* L   = sL[wid];
    float* SX  = sx[wid];
    float* ST1 = st1[wid];
    float* SD  = sdeg[wid];

    #pragma unroll
    for (int i = 0; i < 33; ++i) L[i*32 + lane] = 0.f;
    #pragma unroll
    for (int r = 0; r < 5; ++r) SX[r*32 + lane] = x[(size_t)nb*FFc + r*32 + lane];
    SD[lane] = 0.f;
    __syncwarp();

    int es[8], ed[8];
    float ew[8];
    #pragma unroll
    for (int r = 0; r < 8; ++r){
        const int e = g*EPGc + r*32 + lane;
        es[r] = ei[e]        - nb;
        ed[r] = ei[ETOT + e] - nb;
        ew[r] = ea[e];
        atomicAdd(&SD[es[r]], ew[r]);
    }
    __syncwarp();
    {
        float dv = SD[lane];
        dv = (dv > 0.f) ? rsqrtf(dv) : 0.f;
        __syncwarp();
        SD[lane] = dv;
    }
    __syncwarp();
    #pragma unroll
    for (int r = 0; r < 8; ++r){
        const float nrm = -SD[es[r]] * ew[r] * SD[ed[r]];
        atomicAdd(&L[ed[r]*33 + es[r]], nrm);
    }
    __syncwarp();

    float t1f[5] = {0,0,0,0,0};
    #pragma unroll 4
    for (int s = 0; s < 32; ++s){
        const float l = L[lane*33 + s];
        #pragma unroll
        for (int f = 0; f < 5; ++f) t1f[f] += l * SX[s*5 + f];
    }
    #pragma unroll
    for (int f = 0; f < 5; ++f) ST1[lane*5 + f] = t1f[f];
    __syncwarp();

    float t2f[5] = {0,0,0,0,0};
    #pragma unroll 4
    for (int s = 0; s < 32; ++s){
        const float l = L[lane*33 + s];
        #pragma unroll
        for (int f = 0; f < 5; ++f) t2f[f] += l * ST1[s*5 + f];
    }
    float x0[5];
    #pragma unroll
    for (int f = 0; f < 5; ++f){
        x0[f] = SX[lane*5 + f];
        t2f[f] = 2.f*t2f[f] - x0[f];
    }

    float o[5], s2[5];
    #pragma unroll
    for (int j = 0; j < 5; ++j) o[j] = __ldg(&cb[j]);
    #pragma unroll
    for (int i = 0; i < 5; ++i){
        #pragma unroll
        for (int j = 0; j < 5; ++j)
            o[j] += x0[i]*__ldg(&cw[i*5+j]) + t1f[i]*__ldg(&cw[25+i*5+j]) + t2f[i]*__ldg(&cw[50+i*5+j]);
    }
    #pragma unroll
    for (int j = 0; j < 5; ++j){
        g_y[(size_t)nb*FFc + lane*FFc + j] = o[j];
        s2[j] = o[j]*o[j];
    }
    float s1[5];
    #pragma unroll
    for (int j = 0; j < 5; ++j) s1[j] = o[j];
    #pragma unroll
    for (int off = 16; off; off >>= 1){
        #pragma unroll
        for (int j = 0; j < 5; ++j){
            s1[j] += __shfl_xor_sync(0xffffffffu, s1[j], off);
            s2[j] += __shfl_xor_sync(0xffffffffu, s2[j], off);
        }
    }
    if (lane == 0){
        #pragma unroll
        for (int j = 0; j < 5; ++j){
            atomicAdd(&g_stat[b*16 + j],     s1[j]);
            atomicAdd(&g_stat[b*16 + 8 + j], s2[j]);
        }
    }
}

// ==================== Kernel 2: BN transform (stats precomputed) =====================
__global__ __launch_bounds__(256) void bn_kernel(
    const float* __restrict__ gamma, const float* __restrict__ beta)
{
    const int b = blockIdx.x, tid = threadIdx.x;
    __shared__ float sc[5], sh[5];
    if (tid < 5){
        const float inv = 1.f / (float)(TT*NPGc);
        const float mean = g_stat[b*16 + tid] * inv;
        const float var  = g_stat[b*16 + 8 + tid] * inv - mean*mean;
        const float scl  = gamma[tid] * rsqrtf(var + 1e-5f);
        sc[tid] = scl; sh[tid] = beta[tid] - mean*scl;
    }
    __syncthreads();
    const float* yb = g_y + (size_t)b * TSEQ;
    __half2* hz = (__half2*)(g_hx + (size_t)b*KPAD);
    for (int j = tid; j < HHc/2; j += 256) hz[j] = __half2half2(__float2half(0.f));
    for (int j = tid; j < TT*(KPAD-KTOT); j += 256){
        const int t = j / (KPAD-KTOT), c = j % (KPAD-KTOT);
        g_hx[(size_t)t*SLOT + (size_t)b*KPAD + KTOT + c] = __float2half(0.f);
    }
    for (int nidx = tid; nidx < TT*NPGc; nidx += 256){
        const int t = nidx >> 5, node = nidx & 31;
        const float* p = yb + nidx*FFc;
        __half* ob = g_hx + (size_t)t*SLOT + (size_t)b*KPAD + HHc + node*FFc;
        #pragma unroll
        for (int f = 0; f < 5; ++f) ob[f] = __float2half(sigmf(p[f]*sc[f] + sh[f]));
    }
}

// ==================== Kernel 3: persistent LSTM (exact round-10 core) ================
__global__ __launch_bounds__(256, 1) void lstm_persist_kernel()
{
    extern __shared__ char smem[];
    float* sbias = (float*)(smem + SOFF_BIAS);
    char*  Asm   = smem + SOFF_A;
    char*  Wsm   = smem + SOFF_W;

    const int tid  = threadIdx.x;
    const int lane = tid & 31, warp = tid >> 5;
    const int wm = warp >> 1, wn = warp & 1;          // 4 x 2 warp grid
    const int hblk  = blockIdx.x;                     // 16
    const int mgrp  = blockIdx.y;                     // 8
    const int mbase = mgrp * 128;
    const int hbase = hblk * 32;

    // ---- weights (128 x 704 half) into swizzled smem, once ----
    const __half* Bg = g_Wc + (size_t)(hblk*128)*KPAD;
    for (int i = tid; i < 128*NCHUNK*8; i += 256){
        const int r = i / (NCHUNK*8);
        const int rem = i - r*(NCHUNK*8);
        const int c = rem >> 3, j = rem & 7;
        cpasync16(Wsm + c*16384 + swz((uint32_t)r*128 + j*16),
                  Bg + (size_t)r*KPAD + c*64 + j*8);
    }
    if (tid < 128) sbias[tid] = g_bc[hblk*128 + tid];
    cp_commit();                                       // group: W

    auto fillA = [&](int chunk, int stage, const __half* Ag){
        char* dst = Asm + stage*16384;
        const __half* src = Ag + chunk*64;
        #pragma unroll
        for (int p = 0; p < 4; ++p){
            const int idx = tid + p*256;
            const int r = idx >> 3, j = idx & 7;
            cpasync16(dst + swz((uint32_t)r*128 + j*16), src + (size_t)r*KPAD + j*8);
        }
        cp_commit();
    };

    // prologue: step 0 chunks 8,9 -> stages 0,1
    {
        const __half* Ag0 = g_hx + (size_t)mbase*KPAD;
        fillA(8, 0, Ag0);
        fillA(9, 1, Ag0);
    }

    float c_reg[2][2][4];
    #pragma unroll
    for (int a=0;a<2;a++) for (int b=0;b<2;b++) for (int e=0;e<4;e++) c_reg[a][b][e]=0.f;

    const int gl = lane >> 2, tl = lane & 3;
    int stg = 0;   // stage of chunk being computed this iteration

    for (int t = 0; t < TT; ++t){
        const __half* Ag  = g_hx + (size_t)t*SLOT + (size_t)mbase*KPAD;
        const __half* Agn = g_hx + (size_t)(t+1)*SLOT + (size_t)mbase*KPAD;

        float acc[2][4][2][4];
        #pragma unroll
        for (int a=0;a<2;a++) for (int b=0;b<4;b++) for (int c=0;c<2;c++)
            #pragma unroll
            for (int d=0;d<4;d++) acc[a][b][c][d]=0.f;

        for (int q = 0; q < NCHUNK; ++q){
            if (t == TT-1 && q == NCHUNK-1) cp_wait<0>(); else cp_wait<1>();
            __syncthreads();

            // issue fill for iteration q+2 (stage (stg+2)%3)
            if (!(t == TT-1 && q >= 9)){
                const int fstage = (stg + 2 >= 3) ? stg - 1 : stg + 2;
                if (q == 0){
                    fillA(10, fstage, Ag);
                } else if (q <= 8){
                    if (q == 1 && t > 0){
                        // wait for all 16 producers of this m-group to publish step t h
                        const unsigned* fp = &g_flag[mgrp][0];
                        unsigned ok;
                        do {
                            unsigned f0,f1,f2,f3,f4,f5,f6,f7;
                            asm volatile("ld.relaxed.gpu.v4.u32 {%0,%1,%2,%3}, [%4];"
                                : "=r"(f0),"=r"(f1),"=r"(f2),"=r"(f3) : "l"(fp));
                            asm volatile("ld.relaxed.gpu.v4.u32 {%0,%1,%2,%3}, [%4];"
                                : "=r"(f4),"=r"(f5),"=r"(f6),"=r"(f7) : "l"(fp+4));
                            unsigned g0,g1,g2,g3,g4,g5,g6,g7;
                            asm volatile("ld.relaxed.gpu.v4.u32 {%0,%1,%2,%3}, [%4];"
                                : "=r"(g0),"=r"(g1),"=r"(g2),"=r"(g3) : "l"(fp+8));
                            asm volatile("ld.relaxed.gpu.v4.u32 {%0,%1,%2,%3}, [%4];"
                                : "=r"(g4),"=r"(g5),"=r"(g6),"=r"(g7) : "l"(fp+12));
                            unsigned mn = min(min(min(f0,f1),min(f2,f3)), min(min(f4,f5),min(f6,f7)));
                            mn = min(mn, min(min(min(g0,g1),min(g2,g3)), min(min(g4,g5),min(g6,g7))));
                            ok = (mn >= (unsigned)t);
                        } while (!ok);
                        __threadfence();
                    }
                    fillA(q-1, fstage, Ag);            // h chunks 0..7 of step t
                } else {
                    fillA(q-1, fstage, Agn);           // chunks 8,9 of step t+1 (seq only)
                }
            }

            // compute chunk order[q] from stage stg
            const int c = (q < 3) ? q + 8 : q - 3;
            const char* Wc = Wsm + c*16384;
            const char* Ac = Asm + stg*16384;
            #pragma unroll
            for (int kk = 0; kk < 4; ++kk){
                uint32_t af[2][4];
                #pragma unroll
                for (int mf = 0; mf < 2; ++mf){
                    const uint32_t off = (uint32_t)(wm*32 + mf*16 + (lane&15))*128
                                       + (uint32_t)(kk*16 + ((lane>>4)<<3))*2;
                    ldm_x4(af[mf], Ac + swz(off));
                }
                uint32_t bf[4][4];
                #pragma unroll
                for (int g = 0; g < 4; ++g){
                    const uint32_t off = (uint32_t)(g*32 + wn*16 + (lane&7) + ((lane>>4)&1)*8)*128
                                       + (uint32_t)(kk*16 + ((lane>>3)&1)*8)*2;
                    ldm_x4(bf[g], Wc + swz(off));
                }
                #pragma unroll
                for (int mf = 0; mf < 2; ++mf)
                    #pragma unroll
                    for (int g = 0; g < 4; ++g){
                        mma_f16(acc[mf][g][0], af[mf], bf[g] + 0);
                        mma_f16(acc[mf][g][1], af[mf], bf[g] + 2);
                    }
            }
            stg = (stg + 1 >= 3) ? 0 : stg + 1;
        }

        // epilogue: gates -> c (regs) -> h (half) into slot t+1
        __half* h_out = g_hx + (size_t)(t+1)*SLOT;
        #pragma unroll
        for (int mf = 0; mf < 2; ++mf){
            #pragma unroll
            for (int nf = 0; nf < 2; ++nf){
                const int hloc0 = wn*16 + nf*8 + tl*2;
                #pragma unroll
                for (int rr = 0; rr < 2; ++rr){
                    const int row = mbase + wm*32 + mf*16 + gl + rr*8;
                    float hv[2];
                    #pragma unroll
                    for (int j = 0; j < 2; ++j){
                        const int e = rr*2 + j;
                        const int hl = hloc0 + j;
                        const float iv = acc[mf][0][nf][e] + sbias[hl];
                        const float fv = acc[mf][1][nf][e] + sbias[32 + hl];
                        const float gv = acc[mf][2][nf][e] + sbias[64 + hl];
                        const float ov = acc[mf][3][nf][e] + sbias[96 + hl];
                        const float cn = sigmf(fv)*c_reg[mf][nf][e] + sigmf(iv)*tanhfast(gv);
                        c_reg[mf][nf][e] = cn;
                        hv[j] = sigmf(ov)*tanhfast(cn);
                    }
                    *(__half2*)(h_out + (size_t)row*KPAD + hbase + hloc0) =
                        __halves2half2(__float2half(hv[0]), __float2half(hv[1]));
                }
            }
        }

        // publish h for step t+1 consumers
        __syncthreads();
        if (tid == 0){
            __threadfence();
            asm volatile("st.relaxed.gpu.u32 [%0], %1;"
                :: "l"(&g_flag[mgrp][hblk]), "r"((unsigned)(t+1)) : "memory");
        }
    }

    // reset flags for the next replay (last block to finish)
    __syncthreads();
    if (tid == 0){
        const unsigned d = atomicAdd(&g_done, 1u);
        if (d == 127u){
            for (int i = 0; i < 8; ++i)
                for (int j = 0; j < 16; ++j) g_flag[i][j] = 0u;
            g_done = 0u;
            __threadfence();
        }
    }
}

// ==================== Kernel 4a: final linear partials, split over t =================
__global__ __launch_bounds__(256) void final_part_kernel(const float* __restrict__ linW)
{
    __shared__ float slw[4*HHc];       // linW slice for this t: [o][512]
    const int tid = threadIdx.x;
    const int t = blockIdx.x, mbase = blockIdx.y * 128;

    #pragma unroll
    for (int i = 0; i < 8; ++i){
        const int idx = tid + i*256;            // 2048 floats
        const int o = idx >> 9, h = idx & 511;
        slw[idx] = __ldg(&linW[(size_t)o*(TT*HHc) + t*HHc + h]);
    }
    __syncthreads();

    const int rowl = tid >> 1, half = tid & 1;
    const int h0 = half * 256;
    const __half* hp = g_hx + (size_t)(t+1)*SLOT + (size_t)(mbase + rowl)*KPAD + h0;

    float acc[4] = {0.f, 0.f, 0.f, 0.f};
    #pragma unroll 4
    for (int it = 0; it < 32; ++it){
        const uint4 pk = *(const uint4*)(hp + it*8);
        const __half2* h2 = (const __half2*)&pk;
        #pragma unroll
        for (int p = 0; p < 4; ++p){
            const float2 vv = __half22float2(h2[p]);
            const int h = h0 + it*8 + p*2;
            const float v0 = sigmf(vv.x), v1 = sigmf(vv.y);
            #pragma unroll
            for (int o = 0; o < 4; ++o)
                acc[o] += v0*slw[o*HHc + h] + v1*slw[o*HHc + h + 1];
        }
    }
    #pragma unroll
    for (int o = 0; o < 4; ++o)
        acc[o] += __shfl_xor_sync(0xffffffffu, acc[o], 1);

    if (half == 0){
        float4 w = make_float4(acc[0], acc[1], acc[2], acc[3]);
        *(float4*)(g_part + ((size_t)t*NB + mbase + rowl)*4) = w;
    }
}

// ==================== Kernel 4b: finish — sum partials over t, sigmoid ===============
__global__ __launch_bounds__(256) void final_finish_kernel(
    const float* __restrict__ linb, float* __restrict__ outp)
{
    const int gid = blockIdx.x*256 + threadIdx.x;   // 0..4095
    if (gid >= NB*4) return;
    const int o = gid & 3;
    float sum = 0.f;
    #pragma unroll
    for (int t = 0; t < TT; ++t) sum += g_part[(size_t)t*NB*4 + gid];
    outp[gid] = sigmf(sum + __ldg(&linb[o]));
}

// =====================================================================================
extern "C" void kernel_launch(void* const* d_in, const int* in_sizes, int n_in,
                              void* d_out, int out_size)
{
    const float* x     = (const float*)d_in[0];
    const float* ea    = (const float*)d_in[1];
    const float* cw    = (const float*)d_in[2];
    const float* cb    = (const float*)d_in[3];
    const float* gamma = (const float*)d_in[4];
    const float* beta  = (const float*)d_in[5];
    const float* Wih   = (const float*)d_in[6];
    const float* Whh   = (const float*)d_in[7];
    const float* bih   = (const float*)d_in[8];
    const float* bhh   = (const float*)d_in[9];
    const float* linW  = (const float*)d_in[10];
    const float* linb  = (const float*)d_in[11];
    const int*   ei    = (const int*)  d_in[12];
    float* outp = (float*)d_out;

    cudaFuncSetAttribute(lstm_persist_kernel,
        cudaFuncAttributeMaxDynamicSharedMemorySize, SMEM_SZ);

    pack_kernel<<<1024, 256>>>(Wih, Whh, bih, bhh);
    cheb_kernel<<<NGRAPH/8, 256>>>(x, ea, ei, cw, cb);
    bn_kernel<<<NB, 256>>>(gamma, beta);
    lstm_persist_kernel<<<dim3(16, 8), 256, SMEM_SZ>>>();
    final_part_kernel<<<dim3(TT, 8), 256>>>(linW);
    final_finish_kernel<<<16, 256>>>(linb, outp);
}

// round 14
// speedup vs baseline: 1.7824x; 1.0030x over previous
#include <cuda_runtime.h>
#include <cuda_fp16.h>
#include <cstdint>

#define NB   1024
#define TT   48
#define NPGc 32
#define FFc  5
#define HHc  512
#define EPGc 256
#define NTOT (NB*TT*NPGc)
#define ETOT (NB*TT*EPGc)
#define NGRAPH (NB*TT)
#define SEQW 160
#define TSEQ (TT*SEQW)
#define KTOT 672
#define KPAD 704                   // 11 full chunks of 64, 128B-aligned rows
#define SLOT ((size_t)NB*KPAD)
#define NCHUNK 11

// dynamic smem layout for lstm kernel
#define SOFF_BIAS 0                // 512 B
#define SOFF_A    1024             // 3 stages x 16384
#define SOFF_W    (1024 + 3*16384) // 11 chunks x 16384
#define SMEM_SZ   (SOFF_W + NCHUNK*16384)   // 230400 B

// ---------------- static device scratch --------------------------------------------
__device__ __align__(128) float  g_y  [NTOT*FFc];
__device__ __align__(128) __half g_hx [49*NB*KPAD];   // [t][B][ h(512) | seq(160) | pad ]
__device__ __align__(128) __half g_Wc [4*HHc*KPAD];   // packed [Whh|Wih|0] half
__device__ __align__(128) float  g_bc [4*HHc];
__device__ __align__(128) float  g_stat[NB*16];
__device__ __align__(128) float  g_part[TT*NB*4];     // [t][b][4] final partials
__device__ __align__(128) unsigned g_flag[8][16];     // [mgrp][hblk] step counters
__device__ unsigned g_done = 0;

// HW tanh (sm_75+): 1 MUFU op; sigmoid via tanh identity (1 MUFU + FMA)
__device__ __forceinline__ float tanha(float x){
    float r; asm("tanh.approx.f32 %0, %1;" : "=f"(r) : "f"(x)); return r;
}
__device__ __forceinline__ float sigmf(float x){ return fmaf(0.5f, tanha(0.5f*x), 0.5f); }
__device__ __forceinline__ float tanhfast(float x){ return tanha(x); }

__device__ __forceinline__ void cpasync16(void* dst, const void* src){
    uint32_t d = (uint32_t)__cvta_generic_to_shared(dst);
    asm volatile("cp.async.cg.shared.global [%0], [%1], 16;\n" :: "r"(d), "l"(src));
}
__device__ __forceinline__ void cp_commit(){ asm volatile("cp.async.commit_group;\n"); }
template<int N> __device__ __forceinline__ void cp_wait(){
    asm volatile("cp.async.wait_group %0;\n" :: "n"(N));
}
__device__ __forceinline__ void ldm_x4(uint32_t* r, const void* p){
    uint32_t a = (uint32_t)__cvta_generic_to_shared(p);
    asm volatile("ldmatrix.sync.aligned.m8n8.x4.shared.b16 {%0,%1,%2,%3}, [%4];"
        : "=r"(r[0]), "=r"(r[1]), "=r"(r[2]), "=r"(r[3]) : "r"(a));
}
__device__ __forceinline__ void mma_f16(float* d, const uint32_t* a, const uint32_t* b){
    asm volatile("mma.sync.aligned.m16n8k16.row.col.f32.f16.f16.f32 "
        "{%0,%1,%2,%3}, {%4,%5,%6,%7}, {%8,%9}, {%0,%1,%2,%3};"
        : "+f"(d[0]), "+f"(d[1]), "+f"(d[2]), "+f"(d[3])
        : "r"(a[0]), "r"(a[1]), "r"(a[2]), "r"(a[3]), "r"(b[0]), "r"(b[1]));
}
__device__ __forceinline__ uint32_t swz(uint32_t off){ return off ^ ((off >> 3) & 0x70); }

// ==================== Kernel 0: pack weights (+bias) to half; zero stats =============
__global__ __launch_bounds__(256) void pack_kernel(
    const float* __restrict__ Wih, const float* __restrict__ Whh,
    const float* __restrict__ bih, const float* __restrict__ bhh)
{
    int idx = blockIdx.x*256 + threadIdx.x;
    if (idx < NB*16) g_stat[idx] = 0.f;
    const int total = 4*HHc*KPAD;
    for (; idx < total; idx += gridDim.x*256){
        const int R = idx / KPAD, k = idx - R*KPAD;
        const int hblk = R >> 7, within = R & 127;
        const int g = within >> 5, hloc = within & 31;
        const int p = g*HHc + hblk*32 + hloc;
        float v = 0.f;
        if (k < HHc)       v = Whh[(size_t)p*HHc + k];
        else if (k < KTOT) v = Wih[(size_t)p*SEQW + (k-HHc)];
        g_Wc[idx] = __float2half(v);
        if (k == 0) g_bc[R] = bih[p] + bhh[p];
    }
}

// ==================== Kernel 1: ChebConv — dense L per graph, warp per graph =========
__global__ __launch_bounds__(256) void cheb_kernel(
    const float* __restrict__ x, const float* __restrict__ ea,
    const int* __restrict__ ei, const float* __restrict__ cw,
    const float* __restrict__ cb)
{
    __shared__ float sL[8][32*33];
    __shared__ float sx[8][160], st1[8][160], sdeg[8][32];
    const int tid = threadIdx.x, lane = tid & 31, wid = tid >> 5;
    const int g  = blockIdx.x*8 + wid;
    const int nb = g * NPGc;
    const int b  = g / TT;
    float* L   = sL[wid];
    float* SX  = sx[wid];
    float* ST1 = st1[wid];
    float* SD  = sdeg[wid];

    #pragma unroll
    for (int i = 0; i < 33; ++i) L[i*32 + lane] = 0.f;
    #pragma unroll
    for (int r = 0; r < 5; ++r) SX[r*32 + lane] = x[(size_t)nb*FFc + r*32 + lane];
    SD[lane] = 0.f;
    __syncwarp();

    int es[8], ed[8];
    float ew[8];
    #pragma unroll
    for (int r = 0; r < 8; ++r){
        const int e = g*EPGc + r*32 + lane;
        es[r] = ei[e]        - nb;
        ed[r] = ei[ETOT + e] - nb;
        ew[r] = ea[e];
        atomicAdd(&SD[es[r]], ew[r]);
    }
    __syncwarp();
    {
        float dv = SD[lane];
        dv = (dv > 0.f) ? rsqrtf(dv) : 0.f;
        __syncwarp();
        SD[lane] = dv;
    }
    __syncwarp();
    #pragma unroll
    for (int r = 0; r < 8; ++r){
        const float nrm = -SD[es[r]] * ew[r] * SD[ed[r]];
        atomicAdd(&L[ed[r]*33 + es[r]], nrm);
    }
    __syncwarp();

    float t1f[5] = {0,0,0,0,0};
    #pragma unroll 4
    for (int s = 0; s < 32; ++s){
        const float l = L[lane*33 + s];
        #pragma unroll
        for (int f = 0; f < 5; ++f) t1f[f] += l * SX[s*5 + f];
    }
    #pragma unroll
    for (int f = 0; f < 5; ++f) ST1[lane*5 + f] = t1f[f];
    __syncwarp();

    float t2f[5] = {0,0,0,0,0};
    #pragma unroll 4
    for (int s = 0; s < 32; ++s){
        const float l = L[lane*33 + s];
        #pragma unroll
        for (int f = 0; f < 5; ++f) t2f[f] += l * ST1[s*5 + f];
    }
    float x0[5];
    #pragma unroll
    for (int f = 0; f < 5; ++f){
        x0[f] = SX[lane*5 + f];
        t2f[f] = 2.f*t2f[f] - x0[f];
    }

    float o[5], s2[5];
    #pragma unroll
    for (int j = 0; j < 5; ++j) o[j] = __ldg(&cb[j]);
    #pragma unroll
    for (int i = 0; i < 5; ++i){
        #pragma unroll
        for (int j = 0; j < 5; ++j)
            o[j] += x0[i]*__ldg(&cw[i*5+j]) + t1f[i]*__ldg(&cw[25+i*5+j]) + t2f[i]*__ldg(&cw[50+i*5+j]);
    }
    #pragma unroll
    for (int j = 0; j < 5; ++j){
        g_y[(size_t)nb*FFc + lane*FFc + j] = o[j];
        s2[j] = o[j]*o[j];
    }
    float s1[5];
    #pragma unroll
    for (int j = 0; j < 5; ++j) s1[j] = o[j];
    #pragma unroll
    for (int off = 16; off; off >>= 1){
        #pragma unroll
        for (int j = 0; j < 5; ++j){
            s1[j] += __shfl_xor_sync(0xffffffffu, s1[j], off);
            s2[j] += __shfl_xor_sync(0xffffffffu, s2[j], off);
        }
    }
    if (lane == 0){
        #pragma unroll
        for (int j = 0; j < 5; ++j){
            atomicAdd(&g_stat[b*16 + j],     s1[j]);
            atomicAdd(&g_stat[b*16 + 8 + j], s2[j]);
        }
    }
}

// ==================== Kernel 2: BN transform (stats precomputed) =====================
__global__ __launch_bounds__(256) void bn_kernel(
    const float* __restrict__ gamma, const float* __restrict__ beta)
{
    const int b = blockIdx.x, tid = threadIdx.x;
    __shared__ float sc[5], sh[5];
    if (tid < 5){
        const float inv = 1.f / (float)(TT*NPGc);
        const float mean = g_stat[b*16 + tid] * inv;
        const float var  = g_stat[b*16 + 8 + tid] * inv - mean*mean;
        const float scl  = gamma[tid] * rsqrtf(var + 1e-5f);
        sc[tid] = scl; sh[tid] = beta[tid] - mean*scl;
    }
    __syncthreads();
    const float* yb = g_y + (size_t)b * TSEQ;
    __half2* hz = (__half2*)(g_hx + (size_t)b*KPAD);
    for (int j = tid; j < HHc/2; j += 256) hz[j] = __half2half2(__float2half(0.f));
    for (int j = tid; j < TT*(KPAD-KTOT); j += 256){
        const int t = j / (KPAD-KTOT), c = j % (KPAD-KTOT);
        g_hx[(size_t)t*SLOT + (size_t)b*KPAD + KTOT + c] = __float2half(0.f);
    }
    for (int nidx = tid; nidx < TT*NPGc; nidx += 256){
        const int t = nidx >> 5, node = nidx & 31;
        const float* p = yb + nidx*FFc;
        __half* ob = g_hx + (size_t)t*SLOT + (size_t)b*KPAD + HHc + node*FFc;
        #pragma unroll
        for (int f = 0; f < 5; ++f) ob[f] = __float2half(sigmf(p[f]*sc[f] + sh[f]));
    }
}

// ==================== Kernel 3: persistent LSTM (R10 core + frag double-buffer) ======
__global__ __launch_bounds__(256, 1) void lstm_persist_kernel()
{
    extern __shared__ char smem[];
    float* sbias = (float*)(smem + SOFF_BIAS);
    char*  Asm   = smem + SOFF_A;
    char*  Wsm   = smem + SOFF_W;

    const int tid  = threadIdx.x;
    const int lane = tid & 31, warp = tid >> 5;
    const int wm = warp >> 1, wn = warp & 1;          // 4 x 2 warp grid
    const int hblk  = blockIdx.x;                     // 16
    const int mgrp  = blockIdx.y;                     // 8
    const int mbase = mgrp * 128;
    const int hbase = hblk * 32;

    // ---- weights (128 x 704 half) into swizzled smem, once ----
    const __half* Bg = g_Wc + (size_t)(hblk*128)*KPAD;
    for (int i = tid; i < 128*NCHUNK*8; i += 256){
        const int r = i / (NCHUNK*8);
        const int rem = i - r*(NCHUNK*8);
        const int c = rem >> 3, j = rem & 7;
        cpasync16(Wsm + c*16384 + swz((uint32_t)r*128 + j*16),
                  Bg + (size_t)r*KPAD + c*64 + j*8);
    }
    if (tid < 128) sbias[tid] = g_bc[hblk*128 + tid];
    cp_commit();                                       // group: W

    auto fillA = [&](int chunk, int stage, const __half* Ag){
        char* dst = Asm + stage*16384;
        const __half* src = Ag + chunk*64;
        #pragma unroll
        for (int p = 0; p < 4; ++p){
            const int idx = tid + p*256;
            const int r = idx >> 3, j = idx & 7;
            cpasync16(dst + swz((uint32_t)r*128 + j*16), src + (size_t)r*KPAD + j*8);
        }
        cp_commit();
    };

    // prologue: step 0 chunks 8,9 -> stages 0,1
    {
        const __half* Ag0 = g_hx + (size_t)mbase*KPAD;
        fillA(8, 0, Ag0);
        fillA(9, 1, Ag0);
    }

    float c_reg[2][2][4];
    #pragma unroll
    for (int a=0;a<2;a++) for (int b=0;b<2;b++) for (int e=0;e<4;e++) c_reg[a][b][e]=0.f;

    const int gl = lane >> 2, tl = lane & 3;
    int stg = 0;   // stage of chunk being computed this iteration

    // precomputed ldmatrix lane sub-offsets
    const uint32_t a_rowoff = (uint32_t)(lane & 15) * 128 + (uint32_t)((lane >> 4) << 3) * 2;
    const uint32_t b_rowoff = (uint32_t)((lane & 7) + ((lane >> 4) & 1) * 8) * 128
                            + (uint32_t)(((lane >> 3) & 1) * 8) * 2;

    for (int t = 0; t < TT; ++t){
        const __half* Ag  = g_hx + (size_t)t*SLOT + (size_t)mbase*KPAD;
        const __half* Agn = g_hx + (size_t)(t+1)*SLOT + (size_t)mbase*KPAD;

        float acc[2][4][2][4];
        #pragma unroll
        for (int a=0;a<2;a++) for (int b=0;b<4;b++) for (int c=0;c<2;c++)
            #pragma unroll
            for (int d=0;d<4;d++) acc[a][b][c][d]=0.f;

        for (int q = 0; q < NCHUNK; ++q){
            if (t == TT-1 && q == NCHUNK-1) cp_wait<0>(); else cp_wait<1>();
            __syncthreads();

            // issue fill for iteration q+2 (stage (stg+2)%3)
            if (!(t == TT-1 && q >= 9)){
                const int fstage = (stg + 2 >= 3) ? stg - 1 : stg + 2;
                if (q == 0){
                    fillA(10, fstage, Ag);
                } else if (q <= 8){
                    if (q == 1 && t > 0){
                        // wait for all 16 producers of this m-group to publish step t h
                        const unsigned* fp = &g_flag[mgrp][0];
                        unsigned ok;
                        do {
                            unsigned f0,f1,f2,f3,f4,f5,f6,f7;
                            asm volatile("ld.relaxed.gpu.v4.u32 {%0,%1,%2,%3}, [%4];"
                                : "=r"(f0),"=r"(f1),"=r"(f2),"=r"(f3) : "l"(fp));
                            asm volatile("ld.relaxed.gpu.v4.u32 {%0,%1,%2,%3}, [%4];"
                                : "=r"(f4),"=r"(f5),"=r"(f6),"=r"(f7) : "l"(fp+4));
                            unsigned g0,g1,g2,g3,g4,g5,g6,g7;
                            asm volatile("ld.relaxed.gpu.v4.u32 {%0,%1,%2,%3}, [%4];"
                                : "=r"(g0),"=r"(g1),"=r"(g2),"=r"(g3) : "l"(fp+8));
                            asm volatile("ld.relaxed.gpu.v4.u32 {%0,%1,%2,%3}, [%4];"
                                : "=r"(g4),"=r"(g5),"=r"(g6),"=r"(g7) : "l"(fp+12));
                            unsigned mn = min(min(min(f0,f1),min(f2,f3)), min(min(f4,f5),min(f6,f7)));
                            mn = min(mn, min(min(min(g0,g1),min(g2,g3)), min(min(g4,g5),min(g6,g7))));
                            ok = (mn >= (unsigned)t);
                        } while (!ok);
                        __threadfence();
                    }
                    fillA(q-1, fstage, Ag);            // h chunks 0..7 of step t
                } else {
                    fillA(q-1, fstage, Agn);           // chunks 8,9 of step t+1 (seq only)
                }
            }

            // compute chunk order[q] from stage stg — double-buffered fragments over kk
            const int c = (q < 3) ? q + 8 : q - 3;
            const char* Wc = Wsm + c*16384;
            const char* Ac = Asm + stg*16384;

            uint32_t af[2][2][4];     // [buf][mf][4]
            uint32_t bf[2][4][4];     // [buf][g][4]
            // load kk=0 into buffer 0
            #pragma unroll
            for (int mf = 0; mf < 2; ++mf)
                ldm_x4(af[0][mf], Ac + swz((uint32_t)(wm*32 + mf*16)*128 + a_rowoff));
            #pragma unroll
            for (int g = 0; g < 4; ++g)
                ldm_x4(bf[0][g], Wc + swz((uint32_t)(g*32 + wn*16)*128 + b_rowoff));

            #pragma unroll
            for (int kk = 0; kk < 4; ++kk){
                const int cur = kk & 1, nxt = cur ^ 1;
                if (kk < 3){
                    const uint32_t ko = (uint32_t)((kk+1)*16)*2;
                    #pragma unroll
                    for (int mf = 0; mf < 2; ++mf)
                        ldm_x4(af[nxt][mf],
                               Ac + swz((uint32_t)(wm*32 + mf*16)*128 + a_rowoff + ko));
                    #pragma unroll
                    for (int g = 0; g < 4; ++g)
                        ldm_x4(bf[nxt][g],
                               Wc + swz((uint32_t)(g*32 + wn*16)*128 + b_rowoff + ko));
                }
                #pragma unroll
                for (int mf = 0; mf < 2; ++mf)
                    #pragma unroll
                    for (int g = 0; g < 4; ++g){
                        mma_f16(acc[mf][g][0], af[cur][mf], bf[cur][g] + 0);
                        mma_f16(acc[mf][g][1], af[cur][mf], bf[cur][g] + 2);
                    }
            }
            stg = (stg + 1 >= 3) ? 0 : stg + 1;
        }

        // epilogue: gates -> c (regs) -> h (half) into slot t+1
        __half* h_out = g_hx + (size_t)(t+1)*SLOT;
        #pragma unroll
        for (int mf = 0; mf < 2; ++mf){
            #pragma unroll
            for (int nf = 0; nf < 2; ++nf){
                const int hloc0 = wn*16 + nf*8 + tl*2;
                #pragma unroll
                for (int rr = 0; rr < 2; ++rr){
                    const int row = mbase + wm*32 + mf*16 + gl + rr*8;
                    float hv[2];
                    #pragma unroll
                    for (int j = 0; j < 2; ++j){
                        const int e = rr*2 + j;
                        const int hl = hloc0 + j;
                        const float iv = acc[mf][0][nf][e] + sbias[hl];
                        const float fv = acc[mf][1][nf][e] + sbias[32 + hl];
                        const float gv = acc[mf][2][nf][e] + sbias[64 + hl];
                        const float ov = acc[mf][3][nf][e] + sbias[96 + hl];
                        const float cn = sigmf(fv)*c_reg[mf][nf][e] + sigmf(iv)*tanhfast(gv);
                        c_reg[mf][nf][e] = cn;
                        hv[j] = sigmf(ov)*tanhfast(cn);
                    }
                    *(__half2*)(h_out + (size_t)row*KPAD + hbase + hloc0) =
                        __halves2half2(__float2half(hv[0]), __float2half(hv[1]));
                }
            }
        }

        // publish h for step t+1 consumers
        __syncthreads();
        if (tid == 0){
            __threadfence();
            asm volatile("st.relaxed.gpu.u32 [%0], %1;"
                :: "l"(&g_flag[mgrp][hblk]), "r"((unsigned)(t+1)) : "memory");
        }
    }

    // reset flags for the next replay (last block to finish)
    __syncthreads();
    if (tid == 0){
        const unsigned d = atomicAdd(&g_done, 1u);
        if (d == 127u){
            for (int i = 0; i < 8; ++i)
                for (int j = 0; j < 16; ++j) g_flag[i][j] = 0u;
            g_done = 0u;
            __threadfence();
        }
    }
}

// ==================== Kernel 4a: final linear partials, split over t =================
__global__ __launch_bounds__(256) void final_part_kernel(const float* __restrict__ linW)
{
    __shared__ float slw[4*HHc];       // linW slice for this t: [o][512]
    const int tid = threadIdx.x;
    const int t = blockIdx.x, mbase = blockIdx.y * 128;

    #pragma unroll
    for (int i = 0; i < 8; ++i){
        const int idx = tid + i*256;            // 2048 floats
        const int o = idx >> 9, h = idx & 511;
        slw[idx] = __ldg(&linW[(size_t)o*(TT*HHc) + t*HHc + h]);
    }
    __syncthreads();

    const int rowl = tid >> 1, half = tid & 1;
    const int h0 = half * 256;
    const __half* hp = g_hx + (size_t)(t+1)*SLOT + (size_t)(mbase + rowl)*KPAD + h0;

    float acc[4] = {0.f, 0.f, 0.f, 0.f};
    #pragma unroll 4
    for (int it = 0; it < 32; ++it){
        const uint4 pk = *(const uint4*)(hp + it*8);
        const __half2* h2 = (const __half2*)&pk;
        #pragma unroll
        for (int p = 0; p < 4; ++p){
            const float2 vv = __half22float2(h2[p]);
            const int h = h0 + it*8 + p*2;
            const float v0 = sigmf(vv.x), v1 = sigmf(vv.y);
            #pragma unroll
            for (int o = 0; o < 4; ++o)
                acc[o] += v0*slw[o*HHc + h] + v1*slw[o*HHc + h + 1];
        }
    }
    #pragma unroll
    for (int o = 0; o < 4; ++o)
        acc[o] += __shfl_xor_sync(0xffffffffu, acc[o], 1);

    if (half == 0){
        float4 w = make_float4(acc[0], acc[1], acc[2], acc[3]);
        *(float4*)(g_part + ((size_t)t*NB + mbase + rowl)*4) = w;
    }
}

// ==================== Kernel 4b: finish — sum partials over t, sigmoid ===============
__global__ __launch_bounds__(256) void final_finish_kernel(
    const float* __restrict__ linb, float* __restrict__ outp)
{
    const int gid = blockIdx.x*256 + threadIdx.x;   // 0..4095
    if (gid >= NB*4) return;
    const int o = gid & 3;
    float sum = 0.f;
    #pragma unroll
    for (int t = 0; t < TT; ++t) sum += g_part[(size_t)t*NB*4 + gid];
    outp[gid] = sigmf(sum + __ldg(&linb[o]));
}

// =====================================================================================
extern "C" void kernel_launch(void* const* d_in, const int* in_sizes, int n_in,
                              void* d_out, int out_size)
{
    const float* x     = (const float*)d_in[0];
    const float* ea    = (const float*)d_in[1];
    const float* cw    = (const float*)d_in[2];
    const float* cb    = (const float*)d_in[3];
    const float* gamma = (const float*)d_in[4];
    const float* beta  = (const float*)d_in[5];
    const float* Wih   = (const float*)d_in[6];
    const float* Whh   = (const float*)d_in[7];
    const float* bih   = (const float*)d_in[8];
    const float* bhh   = (const float*)d_in[9];
    const float* linW  = (const float*)d_in[10];
    const float* linb  = (const float*)d_in[11];
    const int*   ei    = (const int*)  d_in[12];
    float* outp = (float*)d_out;

    cudaFuncSetAttribute(lstm_persist_kernel,
        cudaFuncAttributeMaxDynamicSharedMemorySize, SMEM_SZ);

    pack_kernel<<<1024, 256>>>(Wih, Whh, bih, bhh);
    cheb_kernel<<<NGRAPH/8, 256>>>(x, ea, ei, cw, cb);
    bn_kernel<<<NB, 256>>>(gamma, beta);
    lstm_persist_kernel<<<dim3(16, 8), 256, SMEM_SZ>>>();
    final_part_kernel<<<dim3(TT, 8), 256>>>(linW);
    final_finish_kernel<<<16, 256>>>(linb, outp);
}

// round 15
// speedup vs baseline: 1.7869x; 1.0025x over previous
#include <cuda_runtime.h>
#include <cuda_fp16.h>
#include <cstdint>

#define NB   1024
#define TT   48
#define NPGc 32
#define FFc  5
#define HHc  512
#define EPGc 256
#define NTOT (NB*TT*NPGc)
#define ETOT (NB*TT*EPGc)
#define NGRAPH (NB*TT)
#define SEQW 160
#define TSEQ (TT*SEQW)
#define KTOT 672
#define KPAD 704                   // 11 full chunks of 64, 128B-aligned rows
#define SLOT ((size_t)NB*KPAD)
#define NCHUNK 11

// dynamic smem layout for lstm kernel
#define SOFF_BIAS 0                // 512 B
#define SOFF_A    1024             // 3 stages x 16384
#define SOFF_W    (1024 + 3*16384) // 11 chunks x 16384
#define SMEM_SZ   (SOFF_W + NCHUNK*16384)   // 230400 B

// ---------------- static device scratch --------------------------------------------
__device__ __align__(128) float  g_y  [NTOT*FFc];
__device__ __align__(128) __half g_hx [49*NB*KPAD];   // [t][B][ h(512) | seq(160) | pad ]
__device__ __align__(128) __half g_Wc [4*HHc*KPAD];   // packed [Whh|Wih|0] half
__device__ __align__(128) float  g_bc [4*HHc];
__device__ __align__(128) float  g_stat[NB*16];
__device__ __align__(128) float  g_part[TT*NB*4];     // [t][b][4] final partials
__device__ __align__(128) unsigned g_flag[8][16];     // [mgrp][hblk] step counters
__device__ unsigned g_done = 0;

// HW tanh (sm_75+): 1 MUFU op; sigmoid via tanh identity (1 MUFU + FMA)
__device__ __forceinline__ float tanha(float x){
    float r; asm("tanh.approx.f32 %0, %1;" : "=f"(r) : "f"(x)); return r;
}
__device__ __forceinline__ float sigmf(float x){ return fmaf(0.5f, tanha(0.5f*x), 0.5f); }
__device__ __forceinline__ float tanhfast(float x){ return tanha(x); }

__device__ __forceinline__ void cpasync16(void* dst, const void* src){
    uint32_t d = (uint32_t)__cvta_generic_to_shared(dst);
    asm volatile("cp.async.cg.shared.global [%0], [%1], 16;\n" :: "r"(d), "l"(src));
}
__device__ __forceinline__ void cp_commit(){ asm volatile("cp.async.commit_group;\n"); }
template<int N> __device__ __forceinline__ void cp_wait(){
    asm volatile("cp.async.wait_group %0;\n" :: "n"(N));
}
__device__ __forceinline__ void ldm_x4(uint32_t* r, const void* p){
    uint32_t a = (uint32_t)__cvta_generic_to_shared(p);
    asm volatile("ldmatrix.sync.aligned.m8n8.x4.shared.b16 {%0,%1,%2,%3}, [%4];"
        : "=r"(r[0]), "=r"(r[1]), "=r"(r[2]), "=r"(r[3]) : "r"(a));
}
__device__ __forceinline__ void mma_f16(float* d, const uint32_t* a, const uint32_t* b){
    asm volatile("mma.sync.aligned.m16n8k16.row.col.f32.f16.f16.f32 "
        "{%0,%1,%2,%3}, {%4,%5,%6,%7}, {%8,%9}, {%0,%1,%2,%3};"
        : "+f"(d[0]), "+f"(d[1]), "+f"(d[2]), "+f"(d[3])
        : "r"(a[0]), "r"(a[1]), "r"(a[2]), "r"(a[3]), "r"(b[0]), "r"(b[1]));
}
__device__ __forceinline__ uint32_t swz(uint32_t off){ return off ^ ((off >> 3) & 0x70); }

// ==================== Kernel 0: pack weights (+bias) to half; zero stats =============
__global__ __launch_bounds__(256) void pack_kernel(
    const float* __restrict__ Wih, const float* __restrict__ Whh,
    const float* __restrict__ bih, const float* __restrict__ bhh)
{
    int idx = blockIdx.x*256 + threadIdx.x;
    if (idx < NB*16) g_stat[idx] = 0.f;
    const int total = 4*HHc*KPAD;
    for (; idx < total; idx += gridDim.x*256){
        const int R = idx / KPAD, k = idx - R*KPAD;
        const int hblk = R >> 7, within = R & 127;
        const int g = within >> 5, hloc = within & 31;
        const int p = g*HHc + hblk*32 + hloc;
        float v = 0.f;
        if (k < HHc)       v = Whh[(size_t)p*HHc + k];
        else if (k < KTOT) v = Wih[(size_t)p*SEQW + (k-HHc)];
        g_Wc[idx] = __float2half(v);
        if (k == 0) g_bc[R] = bih[p] + bhh[p];
    }
}

// ==================== Kernel 1: ChebConv — dense L per graph, warp per graph =========
__global__ __launch_bounds__(256) void cheb_kernel(
    const float* __restrict__ x, const float* __restrict__ ea,
    const int* __restrict__ ei, const float* __restrict__ cw,
    const float* __restrict__ cb)
{
    __shared__ float sL[8][32*33];
    __shared__ float sx[8][160], st1[8][160], sdeg[8][32];
    const int tid = threadIdx.x, lane = tid & 31, wid = tid >> 5;
    const int g  = blockIdx.x*8 + wid;
    const int nb = g * NPGc;
    const int b  = g / TT;
    float* L   = sL[wid];
    float* SX  = sx[wid];
    float* ST1 = st1[wid];
    float* SD  = sdeg[wid];

    #pragma unroll
    for (int i = 0; i < 33; ++i) L[i*32 + lane] = 0.f;
    #pragma unroll
    for (int r = 0; r < 5; ++r) SX[r*32 + lane] = x[(size_t)nb*FFc + r*32 + lane];
    SD[lane] = 0.f;
    __syncwarp();

    int es[8], ed[8];
    float ew[8];
    #pragma unroll
    for (int r = 0; r < 8; ++r){
        const int e = g*EPGc + r*32 + lane;
        es[r] = ei[e]        - nb;
        ed[r] = ei[ETOT + e] - nb;
        ew[r] = ea[e];
        atomicAdd(&SD[es[r]], ew[r]);
    }
    __syncwarp();
    {
        float dv = SD[lane];
        dv = (dv > 0.f) ? rsqrtf(dv) : 0.f;
        __syncwarp();
        SD[lane] = dv;
    }
    __syncwarp();
    #pragma unroll
    for (int r = 0; r < 8; ++r){
        const float nrm = -SD[es[r]] * ew[r] * SD[ed[r]];
        atomicAdd(&L[ed[r]*33 + es[r]], nrm);
    }
    __syncwarp();

    float t1f[5] = {0,0,0,0,0};
    #pragma unroll 4
    for (int s = 0; s < 32; ++s){
        const float l = L[lane*33 + s];
        #pragma unroll
        for (int f = 0; f < 5; ++f) t1f[f] += l * SX[s*5 + f];
    }
    #pragma unroll
    for (int f = 0; f < 5; ++f) ST1[lane*5 + f] = t1f[f];
    __syncwarp();

    float t2f[5] = {0,0,0,0,0};
    #pragma unroll 4
    for (int s = 0; s < 32; ++s){
        const float l = L[lane*33 + s];
        #pragma unroll
        for (int f = 0; f < 5; ++f) t2f[f] += l * ST1[s*5 + f];
    }
    float x0[5];
    #pragma unroll
    for (int f = 0; f < 5; ++f){
        x0[f] = SX[lane*5 + f];
        t2f[f] = 2.f*t2f[f] - x0[f];
    }

    float o[5], s2[5];
    #pragma unroll
    for (int j = 0; j < 5; ++j) o[j] = __ldg(&cb[j]);
    #pragma unroll
    for (int i = 0; i < 5; ++i){
        #pragma unroll
        for (int j = 0; j < 5; ++j)
            o[j] += x0[i]*__ldg(&cw[i*5+j]) + t1f[i]*__ldg(&cw[25+i*5+j]) + t2f[i]*__ldg(&cw[50+i*5+j]);
    }
    #pragma unroll
    for (int j = 0; j < 5; ++j){
        g_y[(size_t)nb*FFc + lane*FFc + j] = o[j];
        s2[j] = o[j]*o[j];
    }
    float s1[5];
    #pragma unroll
    for (int j = 0; j < 5; ++j) s1[j] = o[j];
    #pragma unroll
    for (int off = 16; off; off >>= 1){
        #pragma unroll
        for (int j = 0; j < 5; ++j){
            s1[j] += __shfl_xor_sync(0xffffffffu, s1[j], off);
            s2[j] += __shfl_xor_sync(0xffffffffu, s2[j], off);
        }
    }
    if (lane == 0){
        #pragma unroll
        for (int j = 0; j < 5; ++j){
            atomicAdd(&g_stat[b*16 + j],     s1[j]);
            atomicAdd(&g_stat[b*16 + 8 + j], s2[j]);
        }
    }
}

// ==================== Kernel 2: BN transform (stats precomputed) =====================
__global__ __launch_bounds__(256) void bn_kernel(
    const float* __restrict__ gamma, const float* __restrict__ beta)
{
    const int b = blockIdx.x, tid = threadIdx.x;
    __shared__ float sc[5], sh[5];
    if (tid < 5){
        const float inv = 1.f / (float)(TT*NPGc);
        const float mean = g_stat[b*16 + tid] * inv;
        const float var  = g_stat[b*16 + 8 + tid] * inv - mean*mean;
        const float scl  = gamma[tid] * rsqrtf(var + 1e-5f);
        sc[tid] = scl; sh[tid] = beta[tid] - mean*scl;
    }
    __syncthreads();
    const float* yb = g_y + (size_t)b * TSEQ;
    __half2* hz = (__half2*)(g_hx + (size_t)b*KPAD);
    for (int j = tid; j < HHc/2; j += 256) hz[j] = __half2half2(__float2half(0.f));
    for (int j = tid; j < TT*(KPAD-KTOT); j += 256){
        const int t = j / (KPAD-KTOT), c = j % (KPAD-KTOT);
        g_hx[(size_t)t*SLOT + (size_t)b*KPAD + KTOT + c] = __float2half(0.f);
    }
    for (int nidx = tid; nidx < TT*NPGc; nidx += 256){
        const int t = nidx >> 5, node = nidx & 31;
        const float* p = yb + nidx*FFc;
        __half* ob = g_hx + (size_t)t*SLOT + (size_t)b*KPAD + HHc + node*FFc;
        #pragma unroll
        for (int f = 0; f < 5; ++f) ob[f] = __float2half(sigmf(p[f]*sc[f] + sh[f]));
    }
}

// ==================== Kernel 3: persistent LSTM (R13 core + cheap sync) ==============
__global__ __launch_bounds__(256, 1) void lstm_persist_kernel()
{
    extern __shared__ char smem[];
    float* sbias = (float*)(smem + SOFF_BIAS);
    char*  Asm   = smem + SOFF_A;
    char*  Wsm   = smem + SOFF_W;

    const int tid  = threadIdx.x;
    const int lane = tid & 31, warp = tid >> 5;
    const int wm = warp >> 1, wn = warp & 1;          // 4 x 2 warp grid
    const int hblk  = blockIdx.x;                     // 16
    const int mgrp  = blockIdx.y;                     // 8
    const int mbase = mgrp * 128;
    const int hbase = hblk * 32;

    // ---- weights (128 x 704 half) into swizzled smem, once ----
    const __half* Bg = g_Wc + (size_t)(hblk*128)*KPAD;
    for (int i = tid; i < 128*NCHUNK*8; i += 256){
        const int r = i / (NCHUNK*8);
        const int rem = i - r*(NCHUNK*8);
        const int c = rem >> 3, j = rem & 7;
        cpasync16(Wsm + c*16384 + swz((uint32_t)r*128 + j*16),
                  Bg + (size_t)r*KPAD + c*64 + j*8);
    }
    if (tid < 128) sbias[tid] = g_bc[hblk*128 + tid];
    cp_commit();                                       // group: W

    auto fillA = [&](int chunk, int stage, const __half* Ag){
        char* dst = Asm + stage*16384;
        const __half* src = Ag + chunk*64;
        #pragma unroll
        for (int p = 0; p < 4; ++p){
            const int idx = tid + p*256;
            const int r = idx >> 3, j = idx & 7;
            cpasync16(dst + swz((uint32_t)r*128 + j*16), src + (size_t)r*KPAD + j*8);
        }
        cp_commit();
    };

    // prologue: step 0 chunks 8,9 -> stages 0,1
    {
        const __half* Ag0 = g_hx + (size_t)mbase*KPAD;
        fillA(8, 0, Ag0);
        fillA(9, 1, Ag0);
    }

    float c_reg[2][2][4];
    #pragma unroll
    for (int a=0;a<2;a++) for (int b=0;b<2;b++) for (int e=0;e<4;e++) c_reg[a][b][e]=0.f;

    const int gl = lane >> 2, tl = lane & 3;
    int stg = 0;   // stage of chunk being computed this iteration

    for (int t = 0; t < TT; ++t){
        const __half* Ag  = g_hx + (size_t)t*SLOT + (size_t)mbase*KPAD;
        const __half* Agn = g_hx + (size_t)(t+1)*SLOT + (size_t)mbase*KPAD;

        float acc[2][4][2][4];
        #pragma unroll
        for (int a=0;a<2;a++) for (int b=0;b<4;b++) for (int c=0;c<2;c++)
            #pragma unroll
            for (int d=0;d<4;d++) acc[a][b][c][d]=0.f;

        for (int q = 0; q < NCHUNK; ++q){
            if (t == TT-1 && q == NCHUNK-1) cp_wait<0>(); else cp_wait<1>();
            __syncthreads();

            // issue fill for iteration q+2 (stage (stg+2)%3)
            if (!(t == TT-1 && q >= 9)){
                const int fstage = (stg + 2 >= 3) ? stg - 1 : stg + 2;
                if (q == 0){
                    fillA(10, fstage, Ag);
                } else if (q <= 8){
                    if (q == 1 && t > 0){
                        // single-thread poll for all 16 producers of this m-group
                        if (tid == 0){
                            const unsigned* fp = &g_flag[mgrp][0];
                            unsigned ok;
                            do {
                                unsigned f0,f1,f2,f3,f4,f5,f6,f7;
                                asm volatile("ld.relaxed.gpu.v4.u32 {%0,%1,%2,%3}, [%4];"
                                    : "=r"(f0),"=r"(f1),"=r"(f2),"=r"(f3) : "l"(fp));
                                asm volatile("ld.relaxed.gpu.v4.u32 {%0,%1,%2,%3}, [%4];"
                                    : "=r"(f4),"=r"(f5),"=r"(f6),"=r"(f7) : "l"(fp+4));
                                unsigned g0,g1,g2,g3,g4,g5,g6,g7;
                                asm volatile("ld.relaxed.gpu.v4.u32 {%0,%1,%2,%3}, [%4];"
                                    : "=r"(g0),"=r"(g1),"=r"(g2),"=r"(g3) : "l"(fp+8));
                                asm volatile("ld.relaxed.gpu.v4.u32 {%0,%1,%2,%3}, [%4];"
                                    : "=r"(g4),"=r"(g5),"=r"(g6),"=r"(g7) : "l"(fp+12));
                                unsigned mn = min(min(min(f0,f1),min(f2,f3)), min(min(f4,f5),min(f6,f7)));
                                mn = min(mn, min(min(min(g0,g1),min(g2,g3)), min(min(g4,g5),min(g6,g7))));
                                ok = (mn >= (unsigned)t);
                            } while (!ok);
                            asm volatile("fence.acq_rel.gpu;" ::: "memory");
                        }
                        __syncthreads();   // propagate acquire to all threads
                    }
                    fillA(q-1, fstage, Ag);            // h chunks 0..7 of step t
                } else {
                    fillA(q-1, fstage, Agn);           // chunks 8,9 of step t+1 (seq only)
                }
            }

            // compute chunk order[q] from stage stg
            const int c = (q < 3) ? q + 8 : q - 3;
            const char* Wc = Wsm + c*16384;
            const char* Ac = Asm + stg*16384;
            #pragma unroll
            for (int kk = 0; kk < 4; ++kk){
                uint32_t af[2][4];
                #pragma unroll
                for (int mf = 0; mf < 2; ++mf){
                    const uint32_t off = (uint32_t)(wm*32 + mf*16 + (lane&15))*128
                                       + (uint32_t)(kk*16 + ((lane>>4)<<3))*2;
                    ldm_x4(af[mf], Ac + swz(off));
                }
                uint32_t bf[4][4];
                #pragma unroll
                for (int g = 0; g < 4; ++g){
                    const uint32_t off = (uint32_t)(g*32 + wn*16 + (lane&7) + ((lane>>4)&1)*8)*128
                                       + (uint32_t)(kk*16 + ((lane>>3)&1)*8)*2;
                    ldm_x4(bf[g], Wc + swz(off));
                }
                #pragma unroll
                for (int mf = 0; mf < 2; ++mf)
                    #pragma unroll
                    for (int g = 0; g < 4; ++g){
                        mma_f16(acc[mf][g][0], af[mf], bf[g] + 0);
                        mma_f16(acc[mf][g][1], af[mf], bf[g] + 2);
                    }
            }
            stg = (stg + 1 >= 3) ? 0 : stg + 1;
        }

        // epilogue: gates -> c (regs) -> h (half) into slot t+1
        __half* h_out = g_hx + (size_t)(t+1)*SLOT;
        #pragma unroll
        for (int mf = 0; mf < 2; ++mf){
            #pragma unroll
            for (int nf = 0; nf < 2; ++nf){
                const int hloc0 = wn*16 + nf*8 + tl*2;
                #pragma unroll
                for (int rr = 0; rr < 2; ++rr){
                    const int row = mbase + wm*32 + mf*16 + gl + rr*8;
                    float hv[2];
                    #pragma unroll
                    for (int j = 0; j < 2; ++j){
                        const int e = rr*2 + j;
                        const int hl = hloc0 + j;
                        const float iv = acc[mf][0][nf][e] + sbias[hl];
                        const float fv = acc[mf][1][nf][e] + sbias[32 + hl];
                        const float gv = acc[mf][2][nf][e] + sbias[64 + hl];
                        const float ov = acc[mf][3][nf][e] + sbias[96 + hl];
                        const float cn = sigmf(fv)*c_reg[mf][nf][e] + sigmf(iv)*tanhfast(gv);
                        c_reg[mf][nf][e] = cn;
                        hv[j] = sigmf(ov)*tanhfast(cn);
                    }
                    *(__half2*)(h_out + (size_t)row*KPAD + hbase + hloc0) =
                        __halves2half2(__float2half(hv[0]), __float2half(hv[1]));
                }
            }
        }

        // publish h for step t+1 consumers (release store; __syncthreads gives hb edge)
        __syncthreads();
        if (tid == 0){
            asm volatile("st.release.gpu.u32 [%0], %1;"
                :: "l"(&g_flag[mgrp][hblk]), "r"((unsigned)(t+1)) : "memory");
        }
    }

    // reset flags for the next replay (last block to finish)
    __syncthreads();
    if (tid == 0){
        const unsigned d = atomicAdd(&g_done, 1u);
        if (d == 127u){
            for (int i = 0; i < 8; ++i)
                for (int j = 0; j < 16; ++j) g_flag[i][j] = 0u;
            g_done = 0u;
            __threadfence();
        }
    }
}

// ==================== Kernel 4a: final linear partials, split over t =================
__global__ __launch_bounds__(256) void final_part_kernel(const float* __restrict__ linW)
{
    __shared__ float slw[4*HHc];       // linW slice for this t: [o][512]
    const int tid = threadIdx.x;
    const int t = blockIdx.x, mbase = blockIdx.y * 128;

    #pragma unroll
    for (int i = 0; i < 8; ++i){
        const int idx = tid + i*256;            // 2048 floats
        const int o = idx >> 9, h = idx & 511;
        slw[idx] = __ldg(&linW[(size_t)o*(TT*HHc) + t*HHc + h]);
    }
    __syncthreads();

    const int rowl = tid >> 1, half = tid & 1;
    const int h0 = half * 256;
    const __half* hp = g_hx + (size_t)(t+1)*SLOT + (size_t)(mbase + rowl)*KPAD + h0;

    float acc[4] = {0.f, 0.f, 0.f, 0.f};
    #pragma unroll 4
    for (int it = 0; it < 32; ++it){
        const uint4 pk = *(const uint4*)(hp + it*8);
        const __half2* h2 = (const __half2*)&pk;
        #pragma unroll
        for (int p = 0; p < 4; ++p){
            const float2 vv = __half22float2(h2[p]);
            const int h = h0 + it*8 + p*2;
            const float v0 = sigmf(vv.x), v1 = sigmf(vv.y);
            #pragma unroll
            for (int o = 0; o < 4; ++o)
                acc[o] += v0*slw[o*HHc + h] + v1*slw[o*HHc + h + 1];
        }
    }
    #pragma unroll
    for (int o = 0; o < 4; ++o)
        acc[o] += __shfl_xor_sync(0xffffffffu, acc[o], 1);

    if (half == 0){
        float4 w = make_float4(acc[0], acc[1], acc[2], acc[3]);
        *(float4*)(g_part + ((size_t)t*NB + mbase + rowl)*4) = w;
    }
}

// ==================== Kernel 4b: finish — sum partials over t, sigmoid ===============
__global__ __launch_bounds__(256) void final_finish_kernel(
    const float* __restrict__ linb, float* __restrict__ outp)
{
    const int gid = blockIdx.x*256 + threadIdx.x;   // 0..4095
    if (gid >= NB*4) return;
    const int o = gid & 3;
    float sum = 0.f;
    #pragma unroll
    for (int t = 0; t < TT; ++t) sum += g_part[(size_t)t*NB*4 + gid];
    outp[gid] = sigmf(sum + __ldg(&linb[o]));
}

// =====================================================================================
extern "C" void kernel_launch(void* const* d_in, const int* in_sizes, int n_in,
                              void* d_out, int out_size)
{
    const float* x     = (const float*)d_in[0];
    const float* ea    = (const float*)d_in[1];
    const float* cw    = (const float*)d_in[2];
    const float* cb    = (const float*)d_in[3];
    const float* gamma = (const float*)d_in[4];
    const float* beta  = (const float*)d_in[5];
    const float* Wih   = (const float*)d_in[6];
    const float* Whh   = (const float*)d_in[7];
    const float* bih   = (const float*)d_in[8];
    const float* bhh   = (const float*)d_in[9];
    const float* linW  = (const float*)d_in[10];
    const float* linb  = (const float*)d_in[11];
    const int*   ei    = (const int*)  d_in[12];
    float* outp = (float*)d_out;

    cudaFuncSetAttribute(lstm_persist_kernel,
        cudaFuncAttributeMaxDynamicSharedMemorySize, SMEM_SZ);

    pack_kernel<<<1024, 256>>>(Wih, Whh, bih, bhh);
    cheb_kernel<<<NGRAPH/8, 256>>>(x, ea, ei, cw, cb);
    bn_kernel<<<NB, 256>>>(gamma, beta);
    lstm_persist_kernel<<<dim3(16, 8), 256, SMEM_SZ>>>();
    final_part_kernel<<<dim3(TT, 8), 256>>>(linW);
    final_finish_kernel<<<16, 256>>>(linb, outp);
}